// round 4
// baseline (speedup 1.0000x reference)
#include <cuda_runtime.h>

#define NCAP 50176
#define ECAP 1700000
#define H 64
#define NCONV 6

// ---------------- static device scratch ----------------
__device__ unsigned long long g_pack[NCAP];     // hi32 = deg, lo32 = sum(sign)+deg*2^20
__device__ int   g_offs[NCAP + 1];
__device__ int   g_cursor[NCAP];
__device__ int   g_csr[ECAP];
__device__ float g_inv[NCAP];
__device__ float g_m[NCAP];
__device__ float g_t[NCAP];
__device__ float g_ya[NCAP];
__device__ float g_yb[NCAP];
__device__ float g_buf1[(size_t)NCAP * H];
__device__ float g_buf2[(size_t)NCAP * H];
__device__ float g_Wt[NCONV * 2 * H * H];       // k-pair interleaved: [conv][kp][c][par]
__device__ int   g_bsum[64];

// ---------------- preprocessing ----------------

__global__ void zero_kernel(int n) {
    int i = blockIdx.x * blockDim.x + threadIdx.x;
    if (i < n) g_pack[i] = 0ULL;
}

__global__ void deg_kernel(const int* __restrict__ ei, int E) {
    int e = blockIdx.x * blockDim.x + threadIdx.x;
    if (e >= E) return;
    int s = ei[e];
    int d = ei[E + e];
    int sg = (s > d) ? 1 : ((s < d) ? -1 : 0);
    unsigned long long add = (1ULL << 32) | (unsigned int)(sg + (1 << 20));
    atomicAdd(&g_pack[d], add);
}

// per-1024-block exclusive scan of deg into g_offs (local), block totals into g_bsum
__global__ void scanA_kernel(int n) {
    __shared__ int sm[32];
    int tid = threadIdx.x;
    int lane = tid & 31, wid = tid >> 5;
    int i = blockIdx.x * 1024 + tid;
    int v = (i < n) ? (int)(g_pack[i] >> 32) : 0;
    int incl = v;
#pragma unroll
    for (int o = 1; o < 32; o <<= 1) {
        int u = __shfl_up_sync(0xffffffffu, incl, o);
        if (lane >= o) incl += u;
    }
    if (lane == 31) sm[wid] = incl;
    __syncthreads();
    if (wid == 0) {
        int t = sm[lane];
#pragma unroll
        for (int o = 1; o < 32; o <<= 1) {
            int u = __shfl_up_sync(0xffffffffu, t, o);
            if (lane >= o) t += u;
        }
        sm[lane] = t;
    }
    __syncthreads();
    int base = (wid > 0) ? sm[wid - 1] : 0;
    if (i < n) g_offs[i] = base + incl - v;
    if (tid == 0) g_bsum[blockIdx.x] = sm[31];
}

// finalize offsets + node params. Each 256-node block sums the g_bsum entries of
// all *preceding* 1024-node chunks (chunk index = (blockIdx.x*256)>>10; all 256
// nodes of a block lie in one chunk since 256 divides 1024).
__global__ void p3_kernel(int nb, int n) {
    __shared__ int s_base;
    int tid = threadIdx.x;
    int chunk = (blockIdx.x * 256) >> 10;
    if (tid < 32) {
        int v0 = (tid < nb && tid < chunk) ? g_bsum[tid] : 0;
        int t2 = tid + 32;
        int v1 = (t2 < nb && t2 < chunk) ? g_bsum[t2] : 0;
        int v = v0 + v1;
#pragma unroll
        for (int o = 16; o > 0; o >>= 1) v += __shfl_xor_sync(0xffffffffu, v, o);
        if (tid == 0) s_base = v;
    }
    __syncthreads();
    int base = s_base;
    int i = blockIdx.x * 256 + tid;
    if (i >= n) return;
    int off = g_offs[i] + base;
    g_offs[i] = off;
    g_cursor[i] = off;
    unsigned long long p = g_pack[i];
    int d = (int)(p >> 32);
    int sgnsum = (int)(unsigned int)(p & 0xffffffffu) - (d << 20);
    float inv = 1.0f / fmaxf((float)d, 1.0f);
    g_inv[i] = inv;
    g_m[i] = d > 0 ? 1.0f : 0.0f;
    g_t[i] = inv * (float)sgnsum;
    if (i == n - 1) g_offs[n] = off + d;
}

__global__ void csr_fill_kernel(const int* __restrict__ ei, int E) {
    int e = blockIdx.x * blockDim.x + threadIdx.x;
    if (e >= E) return;
    int s = ei[e];
    int d = ei[E + e];
    int pos = atomicAdd(&g_cursor[d], 1);
    g_csr[pos] = s;
}

// combined weights, k-pair interleaved: g_Wt[conv][kp][c][par] = Wc[2kp+par][c]
// where Wc rows 0..63 = W1-W2, rows 64..127 = W2
__global__ void wprep_kernel(const float* __restrict__ Wmid) {
    int idx = blockIdx.x * blockDim.x + threadIdx.x;
    if (idx >= NCONV * 2 * H * H) return;
    int conv = idx / (2 * H * H);
    int rem = idx % (2 * H * H);
    int k = rem / H;
    int c = rem % H;
    float v = Wmid[((size_t)conv * 129 + k) * H + c];
    if (k < H) v -= Wmid[((size_t)conv * 129 + H + k) * H + c];
    g_Wt[(size_t)conv * (2 * H * H) + (k >> 1) * 128 + c * 2 + (k & 1)] = v;
}

// ---------------- input layer (fused scalar gather + linear) ----------------

__global__ void inlayer_kernel(const float* __restrict__ x, const float* __restrict__ Win,
                               const float* __restrict__ bin, int n) {
    int warp = (blockIdx.x * blockDim.x + threadIdx.x) >> 5;
    int lane = threadIdx.x & 31;
    if (warp >= n) return;
    int k0 = g_offs[warp], e = g_offs[warp + 1];
    float s = 0.f;
    for (int k = k0 + lane; k < e; k += 32) s += __ldg(&x[g_csr[k]]);
#pragma unroll
    for (int o = 16; o > 0; o >>= 1) s += __shfl_xor_sync(0xffffffffu, s, o);
    float m = g_m[warp], inv = g_inv[warp], t = g_t[warp], xi = x[warp];
    int c0 = 2 * lane;
    float2 w1 = *(const float2*)(Win + c0);
    float2 w2 = *(const float2*)(Win + H + c0);
    float2 w3 = *(const float2*)(Win + 2 * H + c0);
    float2 b  = *(const float2*)(bin + c0);
    float2 o2;
    o2.x = m * (xi * (w1.x - w2.x) + b.x) + inv * s * w2.x + t * w3.x;
    o2.y = m * (xi * (w1.y - w2.y) + b.y) + inv * s * w2.y + t * w3.y;
    *(float2*)(g_buf2 + (size_t)warp * H + c0) = o2;
}

// ---------------- fused mid conv: gather -> smem -> packed-f32x2 GEMM ----------------

#define SM_WS 8192              // 2*H*H floats = 32KB
#define SM_G  16384             // 128 nodes x 128 floats = 64KB
#define SMEM_BYTES ((SM_WS + SM_G) * 4)

__device__ __forceinline__ unsigned long long fma2(unsigned long long a,
                                                   unsigned long long b,
                                                   unsigned long long c) {
    unsigned long long d;
    asm("fma.rn.f32x2 %0, %1, %2, %3;" : "=l"(d) : "l"(a), "l"(b), "l"(c));
    return d;
}

__global__ void __launch_bounds__(256) fused_conv_kernel(
    int conv, const float* __restrict__ bias, const float* __restrict__ wsgn,
    int n, int in_sel, int out_sel, int res_flag) {
    extern __shared__ float smem[];
    float* Ws = smem;
    float* Gs = smem + SM_WS;
    int tid = threadIdx.x;
    int w = tid >> 5, lane = tid & 31;
    int nb0 = blockIdx.x * 128;

    // stage weights (2*H*H = 8192 floats = 2048 float4, 256 threads x 8)
    const float4* Wsrc = (const float4*)(g_Wt + (size_t)conv * (2 * H * H));
    float4* Wdst = (float4*)Ws;
#pragma unroll
    for (int r = 0; r < 8; r++) Wdst[r * 256 + tid] = __ldg(&Wsrc[r * 256 + tid]);

    // gather phase: warp per node, 16 nodes per warp
    const float2* X = (const float2*)(in_sel ? g_buf1 : g_buf2);
#pragma unroll 1
    for (int r8 = 0; r8 < 16; r8++) {
        int node = nb0 + r8 * 8 + w;
        if (node < n) {
            int k = g_offs[node], e = g_offs[node + 1];
            float2 a0 = make_float2(0.f, 0.f), a1 = a0, a2 = a0, a3 = a0;
            for (; k + 4 <= e; k += 4) {
                int j0 = g_csr[k], j1 = g_csr[k + 1], j2 = g_csr[k + 2], j3 = g_csr[k + 3];
                float2 v0 = __ldg(&X[j0 * 32 + lane]);
                float2 v1 = __ldg(&X[j1 * 32 + lane]);
                float2 v2 = __ldg(&X[j2 * 32 + lane]);
                float2 v3 = __ldg(&X[j3 * 32 + lane]);
                a0.x += v0.x; a0.y += v0.y;
                a1.x += v1.x; a1.y += v1.y;
                a2.x += v2.x; a2.y += v2.y;
                a3.x += v3.x; a3.y += v3.y;
            }
            for (; k < e; ++k) {
                float2 v = __ldg(&X[g_csr[k] * 32 + lane]);
                a0.x += v.x; a0.y += v.y;
            }
            float sx = (a0.x + a1.x) + (a2.x + a3.x);
            float sy = (a0.y + a1.y) + (a2.y + a3.y);
            float m = g_m[node], inv = g_inv[node];
            float2 xi = X[node * 32 + lane];
            int row = node - nb0;
            float2* Gr = (float2*)(Gs + row * 128);
            Gr[lane] = make_float2(m * xi.x, m * xi.y);
            Gr[32 + lane] = make_float2(inv * sx, inv * sy);
        }
    }
    __syncthreads();

    // GEMM phase: thread (cg, rq) -> rows rq*8..+7, cols cg*4..+3
    int cg = tid & 15, rq = tid >> 4;
    int r0 = rq * 8;
    unsigned long long acc[8][4];
#pragma unroll
    for (int i = 0; i < 8; i++)
#pragma unroll
        for (int j = 0; j < 4; j++) acc[i][j] = 0ULL;

    const ulonglong2* W2 = (const ulonglong2*)Ws;   // idx = kp*32 + c/2
    const ulonglong2* G2 = (const ulonglong2*)Gs;   // idx = row*32 + k4

#pragma unroll 4
    for (int k4 = 0; k4 < 32; k4++) {
        int kp0 = 2 * k4, kp1 = 2 * k4 + 1;
        ulonglong2 wa0 = W2[kp0 * 32 + cg * 2];     // cols c0,c1 for kp0
        ulonglong2 wb0 = W2[kp0 * 32 + cg * 2 + 1]; // cols c2,c3
        ulonglong2 wa1 = W2[kp1 * 32 + cg * 2];
        ulonglong2 wb1 = W2[kp1 * 32 + cg * 2 + 1];
#pragma unroll
        for (int i = 0; i < 8; i++) {
            ulonglong2 gg = G2[(r0 + i) * 32 + k4]; // gg.x = k-pair kp0, gg.y = kp1
            acc[i][0] = fma2(gg.x, wa0.x, acc[i][0]);
            acc[i][1] = fma2(gg.x, wa0.y, acc[i][1]);
            acc[i][2] = fma2(gg.x, wb0.x, acc[i][2]);
            acc[i][3] = fma2(gg.x, wb0.y, acc[i][3]);
            acc[i][0] = fma2(gg.y, wa1.x, acc[i][0]);
            acc[i][1] = fma2(gg.y, wa1.y, acc[i][1]);
            acc[i][2] = fma2(gg.y, wb1.x, acc[i][2]);
            acc[i][3] = fma2(gg.y, wb1.y, acc[i][3]);
        }
    }

    float* out = out_sel ? g_buf2 : g_buf1;
    int c0 = cg * 4;
    float b0 = bias[c0], b1 = bias[c0 + 1], b2 = bias[c0 + 2], b3 = bias[c0 + 3];
    float q0 = wsgn[c0], q1 = wsgn[c0 + 1], q2 = wsgn[c0 + 2], q3 = wsgn[c0 + 3];
#pragma unroll
    for (int i = 0; i < 8; i++) {
        int r = nb0 + r0 + i;
        if (r >= n) break;
        float m = g_m[r], t = g_t[r];
        float2 p0 = *(float2*)&acc[i][0];
        float2 p1 = *(float2*)&acc[i][1];
        float2 p2 = *(float2*)&acc[i][2];
        float2 p3 = *(float2*)&acc[i][3];
        float o0 = (p0.x + p0.y) + m * b0 + t * q0;
        float o1 = (p1.x + p1.y) + m * b1 + t * q1;
        float o2 = (p2.x + p2.y) + m * b2 + t * q2;
        float o3 = (p3.x + p3.y) + m * b3 + t * q3;
        if (res_flag) {
            float4 rv = *(const float4*)(g_buf2 + (size_t)r * H + c0);
            o0 += rv.x; o1 += rv.y; o2 += rv.z; o3 += rv.w;
        }
        o0 = o0 > 0.f ? o0 : 0.01f * o0;
        o1 = o1 > 0.f ? o1 : 0.01f * o1;
        o2 = o2 > 0.f ? o2 : 0.01f * o2;
        o3 = o3 > 0.f ? o3 : 0.01f * o3;
        *(float4*)(out + (size_t)r * H + c0) = make_float4(o0, o1, o2, o3);
    }
}

// ---------------- output layer ----------------

__global__ void dot_kernel(const float* __restrict__ Wout, int n) {
    int warp = (blockIdx.x * blockDim.x + threadIdx.x) >> 5;
    int lane = threadIdx.x & 31;
    if (warp >= n) return;
    const float2* X = (const float2*)g_buf2;
    float2 v = X[warp * 32 + lane];
    int c0 = 2 * lane, c1 = c0 + 1;
    float b0 = Wout[H + c0], b1 = Wout[H + c1];
    float a0 = Wout[c0] - b0, a1 = Wout[c1] - b1;
    float pa = v.x * a0 + v.y * a1;
    float pb = v.x * b0 + v.y * b1;
#pragma unroll
    for (int o = 16; o > 0; o >>= 1) {
        pa += __shfl_xor_sync(0xffffffffu, pa, o);
        pb += __shfl_xor_sync(0xffffffffu, pb, o);
    }
    if (lane == 0) { g_ya[warp] = pa; g_yb[warp] = pb; }
}

__global__ void final_kernel(const float* __restrict__ x, const float* __restrict__ Wout,
                             const float* __restrict__ bout, float* __restrict__ out, int n) {
    int i = blockIdx.x * blockDim.x + threadIdx.x;
    if (i >= n) return;
    int k = g_offs[i], e = g_offs[i + 1];
    float s0 = 0, s1 = 0, s2 = 0, s3 = 0;
    for (; k + 4 <= e; k += 4) {
        s0 += g_yb[g_csr[k]];
        s1 += g_yb[g_csr[k + 1]];
        s2 += g_yb[g_csr[k + 2]];
        s3 += g_yb[g_csr[k + 3]];
    }
    for (; k < e; ++k) s0 += g_yb[g_csr[k]];
    float S = (s0 + s1) + (s2 + s3);
    out[i] = g_m[i] * (g_ya[i] + bout[0]) + g_inv[i] * S + g_t[i] * Wout[2 * H] + x[i];
}

// ---------------- launch ----------------

extern "C" void kernel_launch(void* const* d_in, const int* in_sizes, int n_in,
                              void* d_out, int out_size) {
    const float* x    = (const float*)d_in[0];
    const int*   ei   = (const int*)d_in[1];
    const float* Win  = (const float*)d_in[2];
    const float* bin  = (const float*)d_in[3];
    const float* Wmid = (const float*)d_in[4];
    const float* bmid = (const float*)d_in[5];
    const float* Wout = (const float*)d_in[6];
    const float* bout = (const float*)d_in[7];
    int N = in_sizes[0];
    int E = in_sizes[1] / 2;
    float* out = (float*)d_out;

    cudaFuncSetAttribute(fused_conv_kernel,
                         cudaFuncAttributeMaxDynamicSharedMemorySize, SMEM_BYTES);

    const int TB = 256;
    int nB = (N + TB - 1) / TB;
    int eB = (E + TB - 1) / TB;
    int NB1024 = (N + 1023) / 1024;
    int gw = (N * 32 + TB - 1) / TB;
    int convB = (N + 127) / 128;

    zero_kernel<<<nB, TB>>>(N);
    deg_kernel<<<eB, TB>>>(ei, E);
    scanA_kernel<<<NB1024, 1024>>>(N);
    p3_kernel<<<nB, TB>>>(NB1024, N);
    csr_fill_kernel<<<eB, TB>>>(ei, E);
    wprep_kernel<<<(NCONV * 2 * H * H + TB - 1) / TB, TB>>>(Wmid);

    inlayer_kernel<<<gw, TB>>>(x, Win, bin, N);

    for (int l = 0; l < 3; l++) {
        int c0 = 2 * l, c1 = 2 * l + 1;
        fused_conv_kernel<<<convB, TB, SMEM_BYTES>>>(
            c0, bmid + (size_t)c0 * H, Wmid + ((size_t)c0 * 129 + 128) * H,
            N, 0, 0, 0);                      // buf2 -> buf1
        fused_conv_kernel<<<convB, TB, SMEM_BYTES>>>(
            c1, bmid + (size_t)c1 * H, Wmid + ((size_t)c1 * 129 + 128) * H,
            N, 1, 1, 1);                      // buf1 -> buf2 (+res)
    }

    dot_kernel<<<gw, TB>>>(Wout, N);
    final_kernel<<<nB, TB>>>(x, Wout, bout, out, N);
}

// round 5
// speedup vs baseline: 1.5918x; 1.5918x over previous
#include <cuda_runtime.h>

#define NCAP 50176
#define ECAP 1700000
#define H 64
#define NCONV 6

// ---------------- static device scratch ----------------
__device__ unsigned long long g_pack[NCAP];     // hi32 = deg, lo32 = sum(sign)+deg*2^20
__device__ int   g_offs[NCAP + 1];
__device__ int   g_cursor[NCAP];
__device__ int   g_csr[ECAP];
__device__ float g_inv[NCAP];
__device__ float g_m[NCAP];
__device__ float g_t[NCAP];
__device__ float g_ya[NCAP];
__device__ float g_yb[NCAP];
__device__ float g_buf1[(size_t)NCAP * H];
__device__ float g_buf2[(size_t)NCAP * H];
__device__ float g_G[(size_t)NCAP * 2 * H];
__device__ float g_Wt[NCONV * 2 * H * H];       // k-pair interleaved: [conv][kp][c][par]
__device__ int   g_bsum[64];

// ---------------- preprocessing ----------------

__global__ void zero_kernel(int n) {
    int i = blockIdx.x * blockDim.x + threadIdx.x;
    if (i < n) g_pack[i] = 0ULL;
}

__global__ void deg_kernel(const int* __restrict__ ei, int E) {
    int e = blockIdx.x * blockDim.x + threadIdx.x;
    if (e >= E) return;
    int s = ei[e];
    int d = ei[E + e];
    int sg = (s > d) ? 1 : ((s < d) ? -1 : 0);
    unsigned long long add = (1ULL << 32) | (unsigned int)(sg + (1 << 20));
    atomicAdd(&g_pack[d], add);
}

// per-1024-block exclusive scan of deg into g_offs (local), block totals into g_bsum
__global__ void scanA_kernel(int n) {
    __shared__ int sm[32];
    int tid = threadIdx.x;
    int lane = tid & 31, wid = tid >> 5;
    int i = blockIdx.x * 1024 + tid;
    int v = (i < n) ? (int)(g_pack[i] >> 32) : 0;
    int incl = v;
#pragma unroll
    for (int o = 1; o < 32; o <<= 1) {
        int u = __shfl_up_sync(0xffffffffu, incl, o);
        if (lane >= o) incl += u;
    }
    if (lane == 31) sm[wid] = incl;
    __syncthreads();
    if (wid == 0) {
        int t = sm[lane];
#pragma unroll
        for (int o = 1; o < 32; o <<= 1) {
            int u = __shfl_up_sync(0xffffffffu, t, o);
            if (lane >= o) t += u;
        }
        sm[lane] = t;
    }
    __syncthreads();
    int base = (wid > 0) ? sm[wid - 1] : 0;
    if (i < n) g_offs[i] = base + incl - v;
    if (tid == 0) g_bsum[blockIdx.x] = sm[31];
}

// finalize offsets + node params; block base re-derived from g_bsum in-kernel
__global__ void p3_kernel(int nb, int n) {
    __shared__ int s_base;
    int tid = threadIdx.x;
    int chunk = (blockIdx.x * 256) >> 10;
    if (tid < 32) {
        int v0 = (tid < nb && tid < chunk) ? g_bsum[tid] : 0;
        int t2 = tid + 32;
        int v1 = (t2 < nb && t2 < chunk) ? g_bsum[t2] : 0;
        int v = v0 + v1;
#pragma unroll
        for (int o = 16; o > 0; o >>= 1) v += __shfl_xor_sync(0xffffffffu, v, o);
        if (tid == 0) s_base = v;
    }
    __syncthreads();
    int base = s_base;
    int i = blockIdx.x * 256 + tid;
    if (i >= n) return;
    int off = g_offs[i] + base;
    g_offs[i] = off;
    g_cursor[i] = off;
    unsigned long long p = g_pack[i];
    int d = (int)(p >> 32);
    int sgnsum = (int)(unsigned int)(p & 0xffffffffu) - (d << 20);
    float inv = 1.0f / fmaxf((float)d, 1.0f);
    g_inv[i] = inv;
    g_m[i] = d > 0 ? 1.0f : 0.0f;
    g_t[i] = inv * (float)sgnsum;
    if (i == n - 1) g_offs[n] = off + d;
}

__global__ void csr_fill_kernel(const int* __restrict__ ei, int E) {
    int e = blockIdx.x * blockDim.x + threadIdx.x;
    if (e >= E) return;
    int s = ei[e];
    int d = ei[E + e];
    int pos = atomicAdd(&g_cursor[d], 1);
    g_csr[pos] = s;
}

// combined weights, k-pair interleaved: g_Wt[conv][kp][c][par] = Wc[2kp+par][c]
// Wc rows 0..63 = W1-W2, rows 64..127 = W2
__global__ void wprep_kernel(const float* __restrict__ Wmid) {
    int idx = blockIdx.x * blockDim.x + threadIdx.x;
    if (idx >= NCONV * 2 * H * H) return;
    int conv = idx / (2 * H * H);
    int rem = idx % (2 * H * H);
    int k = rem / H;
    int c = rem % H;
    float v = Wmid[((size_t)conv * 129 + k) * H + c];
    if (k < H) v -= Wmid[((size_t)conv * 129 + H + k) * H + c];
    g_Wt[(size_t)conv * (2 * H * H) + (k >> 1) * 128 + c * 2 + (k & 1)] = v;
}

// ---------------- input layer (fused scalar gather + linear) ----------------

__global__ void inlayer_kernel(const float* __restrict__ x, const float* __restrict__ Win,
                               const float* __restrict__ bin, int n) {
    int warp = (blockIdx.x * blockDim.x + threadIdx.x) >> 5;
    int lane = threadIdx.x & 31;
    if (warp >= n) return;
    int k0 = g_offs[warp], e = g_offs[warp + 1];
    float s = 0.f;
    for (int k = k0 + lane; k < e; k += 32) s += __ldg(&x[g_csr[k]]);
#pragma unroll
    for (int o = 16; o > 0; o >>= 1) s += __shfl_xor_sync(0xffffffffu, s, o);
    float m = g_m[warp], inv = g_inv[warp], t = g_t[warp], xi = x[warp];
    int c0 = 2 * lane;
    float2 w1 = *(const float2*)(Win + c0);
    float2 w2 = *(const float2*)(Win + H + c0);
    float2 w3 = *(const float2*)(Win + 2 * H + c0);
    float2 b  = *(const float2*)(bin + c0);
    float2 o2;
    o2.x = m * (xi * (w1.x - w2.x) + b.x) + inv * s * w2.x + t * w3.x;
    o2.y = m * (xi * (w1.y - w2.y) + b.y) + inv * s * w2.y + t * w3.y;
    *(float2*)(g_buf2 + (size_t)warp * H + c0) = o2;
}

// ---------------- mid layers: standalone gather (high occupancy) ----------------

// warp-per-node, unroll 8 -> 8 independent in-flight loads per warp
__global__ void gather_kernel(int sel, int n) {
    int warp = (blockIdx.x * blockDim.x + threadIdx.x) >> 5;
    int lane = threadIdx.x & 31;
    if (warp >= n) return;
    const float2* X = (const float2*)(sel ? g_buf1 : g_buf2);
    int k = g_offs[warp], e = g_offs[warp + 1];
    float2 a0 = make_float2(0.f, 0.f), a1 = a0, a2 = a0, a3 = a0;
    for (; k + 8 <= e; k += 8) {
        int j0 = g_csr[k],     j1 = g_csr[k + 1], j2 = g_csr[k + 2], j3 = g_csr[k + 3];
        int j4 = g_csr[k + 4], j5 = g_csr[k + 5], j6 = g_csr[k + 6], j7 = g_csr[k + 7];
        float2 v0 = __ldg(&X[j0 * 32 + lane]);
        float2 v1 = __ldg(&X[j1 * 32 + lane]);
        float2 v2 = __ldg(&X[j2 * 32 + lane]);
        float2 v3 = __ldg(&X[j3 * 32 + lane]);
        float2 v4 = __ldg(&X[j4 * 32 + lane]);
        float2 v5 = __ldg(&X[j5 * 32 + lane]);
        float2 v6 = __ldg(&X[j6 * 32 + lane]);
        float2 v7 = __ldg(&X[j7 * 32 + lane]);
        a0.x += v0.x; a0.y += v0.y;  a1.x += v1.x; a1.y += v1.y;
        a2.x += v2.x; a2.y += v2.y;  a3.x += v3.x; a3.y += v3.y;
        a0.x += v4.x; a0.y += v4.y;  a1.x += v5.x; a1.y += v5.y;
        a2.x += v6.x; a2.y += v6.y;  a3.x += v7.x; a3.y += v7.y;
    }
    for (; k < e; ++k) {
        float2 v = __ldg(&X[g_csr[k] * 32 + lane]);
        a0.x += v.x; a0.y += v.y;
    }
    float sx = (a0.x + a1.x) + (a2.x + a3.x);
    float sy = (a0.y + a1.y) + (a2.y + a3.y);
    float m = g_m[warp], inv = g_inv[warp];
    float2 xi = X[warp * 32 + lane];
    float2* Gr = (float2*)(g_G + (size_t)warp * (2 * H));
    Gr[lane] = make_float2(m * xi.x, m * xi.y);
    Gr[32 + lane] = make_float2(inv * sx, inv * sy);
}

// ---------------- mid layers: packed-f32x2 GEMM ----------------

__device__ __forceinline__ unsigned long long fma2(unsigned long long a,
                                                   unsigned long long b,
                                                   unsigned long long c) {
    unsigned long long d;
    asm("fma.rn.f32x2 %0, %1, %2, %3;" : "=l"(d) : "l"(a), "l"(b), "l"(c));
    return d;
}

__global__ void __launch_bounds__(256) gemm_kernel(
    int conv, const float* __restrict__ bias, const float* __restrict__ wsgn,
    int n, int out_sel, int res_flag) {
    __shared__ float Ws[2 * H * H];         // 32 KB
    int tid = threadIdx.x;
    const float4* Wsrc = (const float4*)(g_Wt + (size_t)conv * (2 * H * H));
    float4* Wdst = (float4*)Ws;
#pragma unroll
    for (int r = 0; r < 8; r++) Wdst[r * 256 + tid] = __ldg(&Wsrc[r * 256 + tid]);
    __syncthreads();

    int cg = tid & 15, rq = tid >> 4;
    int r0 = blockIdx.x * 128 + rq * 8;
    unsigned long long acc[8][4];
#pragma unroll
    for (int i = 0; i < 8; i++)
#pragma unroll
        for (int j = 0; j < 4; j++) acc[i][j] = 0ULL;

    const ulonglong2* W2 = (const ulonglong2*)Ws;               // idx = kp*32 + c/2
    const ulonglong2* G2 = (const ulonglong2*)g_G;              // idx = row*32 + k4

#pragma unroll 4
    for (int k4 = 0; k4 < 32; k4++) {
        int kp0 = 2 * k4, kp1 = 2 * k4 + 1;
        ulonglong2 wa0 = W2[kp0 * 32 + cg * 2];
        ulonglong2 wb0 = W2[kp0 * 32 + cg * 2 + 1];
        ulonglong2 wa1 = W2[kp1 * 32 + cg * 2];
        ulonglong2 wb1 = W2[kp1 * 32 + cg * 2 + 1];
#pragma unroll
        for (int i = 0; i < 8; i++) {
            ulonglong2 gg = __ldg(&G2[(size_t)(r0 + i) * 32 + k4]);
            acc[i][0] = fma2(gg.x, wa0.x, acc[i][0]);
            acc[i][1] = fma2(gg.x, wa0.y, acc[i][1]);
            acc[i][2] = fma2(gg.x, wb0.x, acc[i][2]);
            acc[i][3] = fma2(gg.x, wb0.y, acc[i][3]);
            acc[i][0] = fma2(gg.y, wa1.x, acc[i][0]);
            acc[i][1] = fma2(gg.y, wa1.y, acc[i][1]);
            acc[i][2] = fma2(gg.y, wb1.x, acc[i][2]);
            acc[i][3] = fma2(gg.y, wb1.y, acc[i][3]);
        }
    }

    float* out = out_sel ? g_buf2 : g_buf1;
    int c0 = cg * 4;
    float b0 = bias[c0], b1 = bias[c0 + 1], b2 = bias[c0 + 2], b3 = bias[c0 + 3];
    float q0 = wsgn[c0], q1 = wsgn[c0 + 1], q2 = wsgn[c0 + 2], q3 = wsgn[c0 + 3];
#pragma unroll
    for (int i = 0; i < 8; i++) {
        int r = r0 + i;
        if (r >= n) break;
        float m = g_m[r], t = g_t[r];
        float2 p0 = *(float2*)&acc[i][0];
        float2 p1 = *(float2*)&acc[i][1];
        float2 p2 = *(float2*)&acc[i][2];
        float2 p3 = *(float2*)&acc[i][3];
        float o0 = (p0.x + p0.y) + m * b0 + t * q0;
        float o1 = (p1.x + p1.y) + m * b1 + t * q1;
        float o2 = (p2.x + p2.y) + m * b2 + t * q2;
        float o3 = (p3.x + p3.y) + m * b3 + t * q3;
        if (res_flag) {
            float4 rv = *(const float4*)(g_buf2 + (size_t)r * H + c0);
            o0 += rv.x; o1 += rv.y; o2 += rv.z; o3 += rv.w;
        }
        o0 = o0 > 0.f ? o0 : 0.01f * o0;
        o1 = o1 > 0.f ? o1 : 0.01f * o1;
        o2 = o2 > 0.f ? o2 : 0.01f * o2;
        o3 = o3 > 0.f ? o3 : 0.01f * o3;
        *(float4*)(out + (size_t)r * H + c0) = make_float4(o0, o1, o2, o3);
    }
}

// ---------------- output layer ----------------

__global__ void dot_kernel(const float* __restrict__ Wout, int n) {
    int warp = (blockIdx.x * blockDim.x + threadIdx.x) >> 5;
    int lane = threadIdx.x & 31;
    if (warp >= n) return;
    const float2* X = (const float2*)g_buf2;
    float2 v = X[warp * 32 + lane];
    int c0 = 2 * lane, c1 = c0 + 1;
    float b0 = Wout[H + c0], b1 = Wout[H + c1];
    float a0 = Wout[c0] - b0, a1 = Wout[c1] - b1;
    float pa = v.x * a0 + v.y * a1;
    float pb = v.x * b0 + v.y * b1;
#pragma unroll
    for (int o = 16; o > 0; o >>= 1) {
        pa += __shfl_xor_sync(0xffffffffu, pa, o);
        pb += __shfl_xor_sync(0xffffffffu, pb, o);
    }
    if (lane == 0) { g_ya[warp] = pa; g_yb[warp] = pb; }
}

__global__ void final_kernel(const float* __restrict__ x, const float* __restrict__ Wout,
                             const float* __restrict__ bout, float* __restrict__ out, int n) {
    int i = blockIdx.x * blockDim.x + threadIdx.x;
    if (i >= n) return;
    int k = g_offs[i], e = g_offs[i + 1];
    float s0 = 0, s1 = 0, s2 = 0, s3 = 0;
    for (; k + 4 <= e; k += 4) {
        s0 += g_yb[g_csr[k]];
        s1 += g_yb[g_csr[k + 1]];
        s2 += g_yb[g_csr[k + 2]];
        s3 += g_yb[g_csr[k + 3]];
    }
    for (; k < e; ++k) s0 += g_yb[g_csr[k]];
    float S = (s0 + s1) + (s2 + s3);
    out[i] = g_m[i] * (g_ya[i] + bout[0]) + g_inv[i] * S + g_t[i] * Wout[2 * H] + x[i];
}

// ---------------- launch ----------------

extern "C" void kernel_launch(void* const* d_in, const int* in_sizes, int n_in,
                              void* d_out, int out_size) {
    const float* x    = (const float*)d_in[0];
    const int*   ei   = (const int*)d_in[1];
    const float* Win  = (const float*)d_in[2];
    const float* bin  = (const float*)d_in[3];
    const float* Wmid = (const float*)d_in[4];
    const float* bmid = (const float*)d_in[5];
    const float* Wout = (const float*)d_in[6];
    const float* bout = (const float*)d_in[7];
    int N = in_sizes[0];
    int E = in_sizes[1] / 2;
    float* out = (float*)d_out;

    const int TB = 256;
    int nB = (N + TB - 1) / TB;
    int eB = (E + TB - 1) / TB;
    int NB1024 = (N + 1023) / 1024;
    int gw = (N * 32 + TB - 1) / TB;
    int gemmB = (N + 127) / 128;

    zero_kernel<<<nB, TB>>>(N);
    deg_kernel<<<eB, TB>>>(ei, E);
    scanA_kernel<<<NB1024, 1024>>>(N);
    p3_kernel<<<nB, TB>>>(NB1024, N);
    csr_fill_kernel<<<eB, TB>>>(ei, E);
    wprep_kernel<<<(NCONV * 2 * H * H + TB - 1) / TB, TB>>>(Wmid);

    inlayer_kernel<<<gw, TB>>>(x, Win, bin, N);

    for (int l = 0; l < 3; l++) {
        int c0 = 2 * l, c1 = 2 * l + 1;
        gather_kernel<<<gw, TB>>>(0, N);
        gemm_kernel<<<gemmB, TB>>>(c0, bmid + (size_t)c0 * H,
                                   Wmid + ((size_t)c0 * 129 + 128) * H, N, 0, 0);
        gather_kernel<<<gw, TB>>>(1, N);
        gemm_kernel<<<gemmB, TB>>>(c1, bmid + (size_t)c1 * H,
                                   Wmid + ((size_t)c1 * 129 + 128) * H, N, 1, 1);
    }

    dot_kernel<<<gw, TB>>>(Wout, N);
    final_kernel<<<nB, TB>>>(x, Wout, bout, out, N);
}

// round 6
// speedup vs baseline: 1.7943x; 1.1272x over previous
#include <cuda_runtime.h>

#define NCAP 50176
#define ECAP 1700000
#define H 64
#define NCONV 6

// ---------------- static device scratch ----------------
__device__ unsigned long long g_pack[NCAP];     // hi32 = deg, lo32 = sum(sign)+deg*2^20
__device__ int   g_offs[NCAP + 1];
__device__ int   g_cursor[NCAP];
__device__ int   g_csr[ECAP];
__device__ float g_inv[NCAP];
__device__ float g_m[NCAP];
__device__ float g_t[NCAP];
__device__ float g_ya[NCAP];
__device__ float g_yb[NCAP];
__device__ float g_buf1[(size_t)NCAP * H];
__device__ float g_buf2[(size_t)NCAP * H];
__device__ float g_G[(size_t)NCAP * 2 * H];
__device__ float g_Wc[NCONV * 2 * H * H];       // rows 0..63 = W1-W2, 64..127 = W2
__device__ int   g_bsum[64];
__device__ int   g_bflag[64];

// ---------------- preprocessing ----------------

__global__ void zero_kernel(int n) {
    int i = blockIdx.x * blockDim.x + threadIdx.x;
    if (i < n) g_pack[i] = 0ULL;
    if (i < 64) { g_bflag[i] = 0; g_bsum[i] = 0; }
}

__global__ void deg_kernel(const int* __restrict__ ei, int E) {
    int e = blockIdx.x * blockDim.x + threadIdx.x;
    if (e >= E) return;
    int s = ei[e];
    int d = ei[E + e];
    int sg = (s > d) ? 1 : ((s < d) ? -1 : 0);
    unsigned long long add = (1ULL << 32) | (unsigned int)(sg + (1 << 20));
    atomicAdd(&g_pack[d], add);
}

// merged scan + finalize: per-1024-block scan, decoupled lookback across <=49
// resident blocks, then write offs/cursor/inv/m/t in the same kernel.
__global__ void scanp3_kernel(int n) {
    __shared__ int sm[32];
    __shared__ int s_base;
    int tid = threadIdx.x;
    int lane = tid & 31, wid = tid >> 5;
    int b = blockIdx.x;
    int i = b * 1024 + tid;

    unsigned long long p = (i < n) ? g_pack[i] : 0ULL;
    int v = (int)(p >> 32);
    int incl = v;
#pragma unroll
    for (int o = 1; o < 32; o <<= 1) {
        int u = __shfl_up_sync(0xffffffffu, incl, o);
        if (lane >= o) incl += u;
    }
    if (lane == 31) sm[wid] = incl;
    __syncthreads();
    if (wid == 0) {
        int t = sm[lane];
#pragma unroll
        for (int o = 1; o < 32; o <<= 1) {
            int u = __shfl_up_sync(0xffffffffu, t, o);
            if (lane >= o) t += u;
        }
        sm[lane] = t;
    }
    __syncthreads();
    int wbase = (wid > 0) ? sm[wid - 1] : 0;
    int local_excl = wbase + incl - v;
    int block_total = sm[31];

    // publish this block's total, then look back for predecessors
    if (tid == 0) {
        atomicExch(&g_bsum[b], block_total);
        __threadfence();
        atomicExch(&g_bflag[b], 1);
    }
    if (tid < 32) {
        int base = 0;
        for (int q = tid; q < b; q += 32) {
            while (atomicAdd(&g_bflag[q], 0) == 0) { }
            base += atomicAdd(&g_bsum[q], 0);
        }
#pragma unroll
        for (int o = 16; o > 0; o >>= 1) base += __shfl_xor_sync(0xffffffffu, base, o);
        if (tid == 0) s_base = base;
    }
    __syncthreads();
    if (i >= n) return;
    int off = s_base + local_excl;
    g_offs[i] = off;
    g_cursor[i] = off;
    int d = v;
    int sgnsum = (int)(unsigned int)(p & 0xffffffffu) - (d << 20);
    float inv = 1.0f / fmaxf((float)d, 1.0f);
    g_inv[i] = inv;
    g_m[i] = d > 0 ? 1.0f : 0.0f;
    g_t[i] = inv * (float)sgnsum;
    if (i == n - 1) g_offs[n] = off + d;
}

__global__ void csr_fill_kernel(const int* __restrict__ ei, int E) {
    int e = blockIdx.x * blockDim.x + threadIdx.x;
    if (e >= E) return;
    int s = ei[e];
    int d = ei[E + e];
    int pos = atomicAdd(&g_cursor[d], 1);
    g_csr[pos] = s;
}

// combined weights: rows 0..63 = W1-W2, rows 64..127 = W2
__global__ void wprep_kernel(const float* __restrict__ Wmid) {
    int idx = blockIdx.x * blockDim.x + threadIdx.x;
    if (idx >= NCONV * 2 * H * H) return;
    int conv = idx / (2 * H * H);
    int r = (idx / H) % (2 * H);
    int c = idx % H;
    float v = Wmid[((size_t)conv * 129 + r) * H + c];
    if (r < H) v -= Wmid[((size_t)conv * 129 + H + r) * H + c];
    g_Wc[idx] = v;
}

// ---------------- input layer (fused scalar gather + linear) ----------------

__global__ void inlayer_kernel(const float* __restrict__ x, const float* __restrict__ Win,
                               const float* __restrict__ bin, int n) {
    int warp = (blockIdx.x * blockDim.x + threadIdx.x) >> 5;
    int lane = threadIdx.x & 31;
    if (warp >= n) return;
    int k0 = g_offs[warp], e = g_offs[warp + 1];
    float s = 0.f;
    for (int k = k0 + lane; k < e; k += 32) s += __ldg(&x[g_csr[k]]);
#pragma unroll
    for (int o = 16; o > 0; o >>= 1) s += __shfl_xor_sync(0xffffffffu, s, o);
    float m = g_m[warp], inv = g_inv[warp], t = g_t[warp], xi = x[warp];
    int c0 = 2 * lane;
    float2 w1 = *(const float2*)(Win + c0);
    float2 w2 = *(const float2*)(Win + H + c0);
    float2 w3 = *(const float2*)(Win + 2 * H + c0);
    float2 b  = *(const float2*)(bin + c0);
    float2 o2;
    o2.x = m * (xi * (w1.x - w2.x) + b.x) + inv * s * w2.x + t * w3.x;
    o2.y = m * (xi * (w1.y - w2.y) + b.y) + inv * s * w2.y + t * w3.y;
    *(float2*)(g_buf2 + (size_t)warp * H + c0) = o2;
}

// ---------------- mid layers: gather (R1-proven, unroll 4) ----------------

__global__ void gather_kernel(int sel, int n) {
    int warp = (blockIdx.x * blockDim.x + threadIdx.x) >> 5;
    int lane = threadIdx.x & 31;
    if (warp >= n) return;
    const float2* X = (const float2*)(sel ? g_buf1 : g_buf2);
    int k = g_offs[warp], e = g_offs[warp + 1];
    float2 a0 = make_float2(0.f, 0.f), a1 = a0, a2 = a0, a3 = a0;
    for (; k + 4 <= e; k += 4) {
        int j0 = g_csr[k], j1 = g_csr[k + 1], j2 = g_csr[k + 2], j3 = g_csr[k + 3];
        float2 v0 = X[j0 * 32 + lane];
        float2 v1 = X[j1 * 32 + lane];
        float2 v2 = X[j2 * 32 + lane];
        float2 v3 = X[j3 * 32 + lane];
        a0.x += v0.x; a0.y += v0.y;
        a1.x += v1.x; a1.y += v1.y;
        a2.x += v2.x; a2.y += v2.y;
        a3.x += v3.x; a3.y += v3.y;
    }
    for (; k < e; ++k) {
        float2 v = X[g_csr[k] * 32 + lane];
        a0.x += v.x; a0.y += v.y;
    }
    float sx = (a0.x + a1.x) + (a2.x + a3.x);
    float sy = (a0.y + a1.y) + (a2.y + a3.y);
    float m = g_m[warp], inv = g_inv[warp];
    float2 xi = X[warp * 32 + lane];
    float2* Gr = (float2*)(g_G + (size_t)warp * (2 * H));
    Gr[lane] = make_float2(m * xi.x, m * xi.y);
    Gr[32 + lane] = make_float2(inv * sx, inv * sy);
}

// ---------------- mid layers: GEMM (R1-proven float4 FMA) ----------------

__global__ void gemm_kernel(int conv, const float* __restrict__ bias,
                            const float* __restrict__ wsgn, int n,
                            int out_sel, int res_flag) {
    __shared__ float Ws[2 * H * H];
    int tid = threadIdx.x;
    const float* Wcp = g_Wc + (size_t)conv * (2 * H * H);
    for (int idx = tid; idx < 2 * H * H; idx += 256) Ws[idx] = Wcp[idx];
    __syncthreads();
    int cg = tid & 15, rq = tid >> 4;
    int r0 = blockIdx.x * 128 + rq * 8;
    float acc[8][4];
#pragma unroll
    for (int i = 0; i < 8; i++)
#pragma unroll
        for (int j = 0; j < 4; j++) acc[i][j] = 0.f;
    const float4* Ws4 = (const float4*)Ws;
#pragma unroll 4
    for (int k4 = 0; k4 < 32; k4++) {
        float4 w0 = Ws4[(k4 * 4 + 0) * 16 + cg];
        float4 w1 = Ws4[(k4 * 4 + 1) * 16 + cg];
        float4 w2 = Ws4[(k4 * 4 + 2) * 16 + cg];
        float4 w3 = Ws4[(k4 * 4 + 3) * 16 + cg];
#pragma unroll
        for (int i = 0; i < 8; i++) {
            float4 g = __ldg((const float4*)(g_G + (size_t)(r0 + i) * 128) + k4);
            acc[i][0] += g.x * w0.x + g.y * w1.x + g.z * w2.x + g.w * w3.x;
            acc[i][1] += g.x * w0.y + g.y * w1.y + g.z * w2.y + g.w * w3.y;
            acc[i][2] += g.x * w0.z + g.y * w1.z + g.z * w2.z + g.w * w3.z;
            acc[i][3] += g.x * w0.w + g.y * w1.w + g.z * w2.w + g.w * w3.w;
        }
    }
    float* out = out_sel ? g_buf2 : g_buf1;
    int c0 = cg * 4;
    float b0 = bias[c0], b1 = bias[c0 + 1], b2 = bias[c0 + 2], b3 = bias[c0 + 3];
    float q0 = wsgn[c0], q1 = wsgn[c0 + 1], q2 = wsgn[c0 + 2], q3 = wsgn[c0 + 3];
#pragma unroll
    for (int i = 0; i < 8; i++) {
        int r = r0 + i;
        if (r >= n) break;
        float m = g_m[r], t = g_t[r];
        float o0 = acc[i][0] + m * b0 + t * q0;
        float o1 = acc[i][1] + m * b1 + t * q1;
        float o2 = acc[i][2] + m * b2 + t * q2;
        float o3 = acc[i][3] + m * b3 + t * q3;
        if (res_flag) {
            float4 rv = *(const float4*)(g_buf2 + (size_t)r * H + c0);
            o0 += rv.x; o1 += rv.y; o2 += rv.z; o3 += rv.w;
        }
        o0 = o0 > 0.f ? o0 : 0.01f * o0;
        o1 = o1 > 0.f ? o1 : 0.01f * o1;
        o2 = o2 > 0.f ? o2 : 0.01f * o2;
        o3 = o3 > 0.f ? o3 : 0.01f * o3;
        *(float4*)(out + (size_t)r * H + c0) = make_float4(o0, o1, o2, o3);
    }
}

// ---------------- output layer ----------------

__global__ void dot_kernel(const float* __restrict__ Wout, int n) {
    int warp = (blockIdx.x * blockDim.x + threadIdx.x) >> 5;
    int lane = threadIdx.x & 31;
    if (warp >= n) return;
    const float2* X = (const float2*)g_buf2;
    float2 v = X[warp * 32 + lane];
    int c0 = 2 * lane, c1 = c0 + 1;
    float b0 = Wout[H + c0], b1 = Wout[H + c1];
    float a0 = Wout[c0] - b0, a1 = Wout[c1] - b1;
    float pa = v.x * a0 + v.y * a1;
    float pb = v.x * b0 + v.y * b1;
#pragma unroll
    for (int o = 16; o > 0; o >>= 1) {
        pa += __shfl_xor_sync(0xffffffffu, pa, o);
        pb += __shfl_xor_sync(0xffffffffu, pb, o);
    }
    if (lane == 0) { g_ya[warp] = pa; g_yb[warp] = pb; }
}

__global__ void final_kernel(const float* __restrict__ x, const float* __restrict__ Wout,
                             const float* __restrict__ bout, float* __restrict__ out, int n) {
    int i = blockIdx.x * blockDim.x + threadIdx.x;
    if (i >= n) return;
    int k = g_offs[i], e = g_offs[i + 1];
    float s0 = 0, s1 = 0, s2 = 0, s3 = 0;
    for (; k + 4 <= e; k += 4) {
        s0 += g_yb[g_csr[k]];
        s1 += g_yb[g_csr[k + 1]];
        s2 += g_yb[g_csr[k + 2]];
        s3 += g_yb[g_csr[k + 3]];
    }
    for (; k < e; ++k) s0 += g_yb[g_csr[k]];
    float S = (s0 + s1) + (s2 + s3);
    out[i] = g_m[i] * (g_ya[i] + bout[0]) + g_inv[i] * S + g_t[i] * Wout[2 * H] + x[i];
}

// ---------------- launch ----------------

extern "C" void kernel_launch(void* const* d_in, const int* in_sizes, int n_in,
                              void* d_out, int out_size) {
    const float* x    = (const float*)d_in[0];
    const int*   ei   = (const int*)d_in[1];
    const float* Win  = (const float*)d_in[2];
    const float* bin  = (const float*)d_in[3];
    const float* Wmid = (const float*)d_in[4];
    const float* bmid = (const float*)d_in[5];
    const float* Wout = (const float*)d_in[6];
    const float* bout = (const float*)d_in[7];
    int N = in_sizes[0];
    int E = in_sizes[1] / 2;
    float* out = (float*)d_out;

    const int TB = 256;
    int nB = (N + TB - 1) / TB;
    int eB = (E + TB - 1) / TB;
    int NB1024 = (N + 1023) / 1024;
    int gw = (N * 32 + TB - 1) / TB;
    int gemmB = (N + 127) / 128;

    zero_kernel<<<nB, TB>>>(N);            // 1
    deg_kernel<<<eB, TB>>>(ei, E);         // 2
    scanp3_kernel<<<NB1024, 1024>>>(N);    // 3
    csr_fill_kernel<<<eB, TB>>>(ei, E);    // 4  <- profiled slot
    wprep_kernel<<<(NCONV * 2 * H * H + TB - 1) / TB, TB>>>(Wmid);  // 5
    inlayer_kernel<<<gw, TB>>>(x, Win, bin, N);                     // 6

    for (int l = 0; l < 3; l++) {
        int c0 = 2 * l, c1 = 2 * l + 1;
        gather_kernel<<<gw, TB>>>(0, N);
        gemm_kernel<<<gemmB, TB>>>(c0, bmid + (size_t)c0 * H,
                                   Wmid + ((size_t)c0 * 129 + 128) * H, N, 0, 0);
        gather_kernel<<<gw, TB>>>(1, N);
        gemm_kernel<<<gemmB, TB>>>(c1, bmid + (size_t)c1 * H,
                                   Wmid + ((size_t)c1 * 129 + 128) * H, N, 1, 1);
    }

    dot_kernel<<<gw, TB>>>(Wout, N);
    final_kernel<<<nB, TB>>>(x, Wout, bout, out, N);
}

// round 7
// speedup vs baseline: 1.8262x; 1.0178x over previous
#include <cuda_runtime.h>

#define NCAP 50176
#define ECAP 1700000
#define H 64
#define NCONV 6

// ---------------- static device scratch ----------------
__device__ unsigned long long g_pack[NCAP];     // hi32 = deg, lo32 = sum(sign)+deg*2^20
__device__ int   g_offs[NCAP + 1];
__device__ int   g_cursor[NCAP];
__device__ int   g_csr[ECAP];
__device__ float g_inv[NCAP];
__device__ float g_m[NCAP];
__device__ float g_t[NCAP];
__device__ float g_ya[NCAP];
__device__ float g_yb[NCAP];
__device__ float g_buf1[(size_t)NCAP * H];
__device__ float g_buf2[(size_t)NCAP * H];
__device__ float g_G[(size_t)NCAP * 2 * H];
__device__ float g_Wc[NCONV * 2 * H * H];       // rows 0..63 = W1-W2, 64..127 = W2
__device__ int   g_bsum[64];
__device__ int   g_bflag[64];

// ---------------- preprocessing ----------------

__global__ void zero_kernel(int n) {
    int i = blockIdx.x * blockDim.x + threadIdx.x;
    if (i < n) g_pack[i] = 0ULL;
    if (i < 64) { g_bflag[i] = 0; g_bsum[i] = 0; }
}

__global__ void deg_kernel(const int* __restrict__ ei, int E) {
    int e = blockIdx.x * blockDim.x + threadIdx.x;
    if (e >= E) return;
    int s = ei[e];
    int d = ei[E + e];
    int sg = (s > d) ? 1 : ((s < d) ? -1 : 0);
    unsigned long long add = (1ULL << 32) | (unsigned int)(sg + (1 << 20));
    atomicAdd(&g_pack[d], add);
}

// merged scan + finalize: per-1024-block scan, decoupled lookback across <=49
// resident blocks, then write offs/cursor/inv/m/t in the same kernel.
__global__ void scanp3_kernel(int n) {
    __shared__ int sm[32];
    __shared__ int s_base;
    int tid = threadIdx.x;
    int lane = tid & 31, wid = tid >> 5;
    int b = blockIdx.x;
    int i = b * 1024 + tid;

    unsigned long long p = (i < n) ? g_pack[i] : 0ULL;
    int v = (int)(p >> 32);
    int incl = v;
#pragma unroll
    for (int o = 1; o < 32; o <<= 1) {
        int u = __shfl_up_sync(0xffffffffu, incl, o);
        if (lane >= o) incl += u;
    }
    if (lane == 31) sm[wid] = incl;
    __syncthreads();
    if (wid == 0) {
        int t = sm[lane];
#pragma unroll
        for (int o = 1; o < 32; o <<= 1) {
            int u = __shfl_up_sync(0xffffffffu, t, o);
            if (lane >= o) t += u;
        }
        sm[lane] = t;
    }
    __syncthreads();
    int wbase = (wid > 0) ? sm[wid - 1] : 0;
    int local_excl = wbase + incl - v;
    int block_total = sm[31];

    if (tid == 0) {
        atomicExch(&g_bsum[b], block_total);
        __threadfence();
        atomicExch(&g_bflag[b], 1);
    }
    if (tid < 32) {
        int base = 0;
        for (int q = tid; q < b; q += 32) {
            while (atomicAdd(&g_bflag[q], 0) == 0) { }
            base += atomicAdd(&g_bsum[q], 0);
        }
#pragma unroll
        for (int o = 16; o > 0; o >>= 1) base += __shfl_xor_sync(0xffffffffu, base, o);
        if (tid == 0) s_base = base;
    }
    __syncthreads();
    if (i >= n) return;
    int off = s_base + local_excl;
    g_offs[i] = off;
    g_cursor[i] = off;
    int d = v;
    int sgnsum = (int)(unsigned int)(p & 0xffffffffu) - (d << 20);
    float inv = 1.0f / fmaxf((float)d, 1.0f);
    g_inv[i] = inv;
    g_m[i] = d > 0 ? 1.0f : 0.0f;
    g_t[i] = inv * (float)sgnsum;
    if (i == n - 1) g_offs[n] = off + d;
}

__global__ void csr_fill_kernel(const int* __restrict__ ei, int E) {
    int e = blockIdx.x * blockDim.x + threadIdx.x;
    if (e >= E) return;
    int s = ei[e];
    int d = ei[E + e];
    int pos = atomicAdd(&g_cursor[d], 1);
    g_csr[pos] = s;
}

// combined weights: rows 0..63 = W1-W2, rows 64..127 = W2
__global__ void wprep_kernel(const float* __restrict__ Wmid) {
    int idx = blockIdx.x * blockDim.x + threadIdx.x;
    if (idx >= NCONV * 2 * H * H) return;
    int conv = idx / (2 * H * H);
    int r = (idx / H) % (2 * H);
    int c = idx % H;
    float v = Wmid[((size_t)conv * 129 + r) * H + c];
    if (r < H) v -= Wmid[((size_t)conv * 129 + H + r) * H + c];
    g_Wc[idx] = v;
}

// ---------------- input layer (fused scalar gather + linear) ----------------

__global__ void inlayer_kernel(const float* __restrict__ x, const float* __restrict__ Win,
                               const float* __restrict__ bin, int n) {
    int warp = (blockIdx.x * blockDim.x + threadIdx.x) >> 5;
    int lane = threadIdx.x & 31;
    if (warp >= n) return;
    int k0 = g_offs[warp], e = g_offs[warp + 1];
    float s = 0.f;
    for (int k = k0 + lane; k < e; k += 32) s += __ldg(&x[g_csr[k]]);
#pragma unroll
    for (int o = 16; o > 0; o >>= 1) s += __shfl_xor_sync(0xffffffffu, s, o);
    float m = g_m[warp], inv = g_inv[warp], t = g_t[warp], xi = x[warp];
    int c0 = 2 * lane;
    float2 w1 = *(const float2*)(Win + c0);
    float2 w2 = *(const float2*)(Win + H + c0);
    float2 w3 = *(const float2*)(Win + 2 * H + c0);
    float2 b  = *(const float2*)(bin + c0);
    float2 o2;
    o2.x = m * (xi * (w1.x - w2.x) + b.x) + inv * s * w2.x + t * w3.x;
    o2.y = m * (xi * (w1.y - w2.y) + b.y) + inv * s * w2.y + t * w3.y;
    *(float2*)(g_buf2 + (size_t)warp * H + c0) = o2;
}

// ---------------- mid layers: paired-edge float4 gather ----------------
// Half-warp per edge: lanes 0-15 load edge e's row, lanes 16-31 edge e+1's row,
// one LDG.128 per lane (16 lanes x 16B = full 256B row). Halves warp-level LDG
// instruction count per edge vs the float2 version.

__global__ void gather_kernel(int sel, int n) {
    int warp = (blockIdx.x * blockDim.x + threadIdx.x) >> 5;
    int lane = threadIdx.x & 31;
    if (warp >= n) return;
    const float4* X4 = (const float4*)(sel ? g_buf1 : g_buf2);
    int hl = lane & 15;
    int par = lane >> 4;                     // 0: even edge, 1: odd edge
    int k = g_offs[warp], e = g_offs[warp + 1];
    float4 a0 = make_float4(0.f, 0.f, 0.f, 0.f), a1 = a0;
    for (; k + 8 <= e; k += 8) {
        int j0 = g_csr[k + par];
        int j1 = g_csr[k + 2 + par];
        int j2 = g_csr[k + 4 + par];
        int j3 = g_csr[k + 6 + par];
        float4 v0 = X4[(size_t)j0 * 16 + hl];
        float4 v1 = X4[(size_t)j1 * 16 + hl];
        float4 v2 = X4[(size_t)j2 * 16 + hl];
        float4 v3 = X4[(size_t)j3 * 16 + hl];
        a0.x += v0.x; a0.y += v0.y; a0.z += v0.z; a0.w += v0.w;
        a1.x += v1.x; a1.y += v1.y; a1.z += v1.z; a1.w += v1.w;
        a0.x += v2.x; a0.y += v2.y; a0.z += v2.z; a0.w += v2.w;
        a1.x += v3.x; a1.y += v3.y; a1.z += v3.z; a1.w += v3.w;
    }
    for (; k + 2 <= e; k += 2) {
        int j = g_csr[k + par];
        float4 v = X4[(size_t)j * 16 + hl];
        a0.x += v.x; a0.y += v.y; a0.z += v.z; a0.w += v.w;
    }
    if (k < e && par == 0) {                 // last odd edge: lanes 0-15 only
        int j = g_csr[k];
        float4 v = X4[(size_t)j * 16 + hl];
        a1.x += v.x; a1.y += v.y; a1.z += v.z; a1.w += v.w;
    }
    float4 s;
    s.x = a0.x + a1.x; s.y = a0.y + a1.y; s.z = a0.z + a1.z; s.w = a0.w + a1.w;
    s.x += __shfl_xor_sync(0xffffffffu, s.x, 16);
    s.y += __shfl_xor_sync(0xffffffffu, s.y, 16);
    s.z += __shfl_xor_sync(0xffffffffu, s.z, 16);
    s.w += __shfl_xor_sync(0xffffffffu, s.w, 16);
    float m = g_m[warp], inv = g_inv[warp];
    float4* Gr = (float4*)(g_G + (size_t)warp * (2 * H));
    if (par == 0) {
        float4 xi = X4[(size_t)warp * 16 + hl];
        Gr[hl] = make_float4(m * xi.x, m * xi.y, m * xi.z, m * xi.w);
    } else {
        Gr[16 + hl] = make_float4(inv * s.x, inv * s.y, inv * s.z, inv * s.w);
    }
}

// ---------------- mid layers: GEMM (float4 FMA, at fp32 roofline) ----------------

__global__ void gemm_kernel(int conv, const float* __restrict__ bias,
                            const float* __restrict__ wsgn, int n,
                            int out_sel, int res_flag) {
    __shared__ float Ws[2 * H * H];
    int tid = threadIdx.x;
    const float* Wcp = g_Wc + (size_t)conv * (2 * H * H);
    for (int idx = tid; idx < 2 * H * H; idx += 256) Ws[idx] = Wcp[idx];
    __syncthreads();
    int cg = tid & 15, rq = tid >> 4;
    int r0 = blockIdx.x * 128 + rq * 8;
    float acc[8][4];
#pragma unroll
    for (int i = 0; i < 8; i++)
#pragma unroll
        for (int j = 0; j < 4; j++) acc[i][j] = 0.f;
    const float4* Ws4 = (const float4*)Ws;
#pragma unroll 4
    for (int k4 = 0; k4 < 32; k4++) {
        float4 w0 = Ws4[(k4 * 4 + 0) * 16 + cg];
        float4 w1 = Ws4[(k4 * 4 + 1) * 16 + cg];
        float4 w2 = Ws4[(k4 * 4 + 2) * 16 + cg];
        float4 w3 = Ws4[(k4 * 4 + 3) * 16 + cg];
#pragma unroll
        for (int i = 0; i < 8; i++) {
            float4 g = __ldg((const float4*)(g_G + (size_t)(r0 + i) * 128) + k4);
            acc[i][0] += g.x * w0.x + g.y * w1.x + g.z * w2.x + g.w * w3.x;
            acc[i][1] += g.x * w0.y + g.y * w1.y + g.z * w2.y + g.w * w3.y;
            acc[i][2] += g.x * w0.z + g.y * w1.z + g.z * w2.z + g.w * w3.z;
            acc[i][3] += g.x * w0.w + g.y * w1.w + g.z * w2.w + g.w * w3.w;
        }
    }
    float* out = out_sel ? g_buf2 : g_buf1;
    int c0 = cg * 4;
    float b0 = bias[c0], b1 = bias[c0 + 1], b2 = bias[c0 + 2], b3 = bias[c0 + 3];
    float q0 = wsgn[c0], q1 = wsgn[c0 + 1], q2 = wsgn[c0 + 2], q3 = wsgn[c0 + 3];
#pragma unroll
    for (int i = 0; i < 8; i++) {
        int r = r0 + i;
        if (r >= n) break;
        float m = g_m[r], t = g_t[r];
        float o0 = acc[i][0] + m * b0 + t * q0;
        float o1 = acc[i][1] + m * b1 + t * q1;
        float o2 = acc[i][2] + m * b2 + t * q2;
        float o3 = acc[i][3] + m * b3 + t * q3;
        if (res_flag) {
            float4 rv = *(const float4*)(g_buf2 + (size_t)r * H + c0);
            o0 += rv.x; o1 += rv.y; o2 += rv.z; o3 += rv.w;
        }
        o0 = o0 > 0.f ? o0 : 0.01f * o0;
        o1 = o1 > 0.f ? o1 : 0.01f * o1;
        o2 = o2 > 0.f ? o2 : 0.01f * o2;
        o3 = o3 > 0.f ? o3 : 0.01f * o3;
        *(float4*)(out + (size_t)r * H + c0) = make_float4(o0, o1, o2, o3);
    }
}

// ---------------- output layer ----------------

__global__ void dot_kernel(const float* __restrict__ Wout, int n) {
    int warp = (blockIdx.x * blockDim.x + threadIdx.x) >> 5;
    int lane = threadIdx.x & 31;
    if (warp >= n) return;
    const float2* X = (const float2*)g_buf2;
    float2 v = X[warp * 32 + lane];
    int c0 = 2 * lane, c1 = c0 + 1;
    float b0 = Wout[H + c0], b1 = Wout[H + c1];
    float a0 = Wout[c0] - b0, a1 = Wout[c1] - b1;
    float pa = v.x * a0 + v.y * a1;
    float pb = v.x * b0 + v.y * b1;
#pragma unroll
    for (int o = 16; o > 0; o >>= 1) {
        pa += __shfl_xor_sync(0xffffffffu, pa, o);
        pb += __shfl_xor_sync(0xffffffffu, pb, o);
    }
    if (lane == 0) { g_ya[warp] = pa; g_yb[warp] = pb; }
}

__global__ void final_kernel(const float* __restrict__ x, const float* __restrict__ Wout,
                             const float* __restrict__ bout, float* __restrict__ out, int n) {
    int i = blockIdx.x * blockDim.x + threadIdx.x;
    if (i >= n) return;
    int k = g_offs[i], e = g_offs[i + 1];
    float s0 = 0, s1 = 0, s2 = 0, s3 = 0;
    for (; k + 4 <= e; k += 4) {
        s0 += g_yb[g_csr[k]];
        s1 += g_yb[g_csr[k + 1]];
        s2 += g_yb[g_csr[k + 2]];
        s3 += g_yb[g_csr[k + 3]];
    }
    for (; k < e; ++k) s0 += g_yb[g_csr[k]];
    float S = (s0 + s1) + (s2 + s3);
    out[i] = g_m[i] * (g_ya[i] + bout[0]) + g_inv[i] * S + g_t[i] * Wout[2 * H] + x[i];
}

// ---------------- launch ----------------

extern "C" void kernel_launch(void* const* d_in, const int* in_sizes, int n_in,
                              void* d_out, int out_size) {
    const float* x    = (const float*)d_in[0];
    const int*   ei   = (const int*)d_in[1];
    const float* Win  = (const float*)d_in[2];
    const float* bin  = (const float*)d_in[3];
    const float* Wmid = (const float*)d_in[4];
    const float* bmid = (const float*)d_in[5];
    const float* Wout = (const float*)d_in[6];
    const float* bout = (const float*)d_in[7];
    int N = in_sizes[0];
    int E = in_sizes[1] / 2;
    float* out = (float*)d_out;

    const int TB = 256;
    int nB = (N + TB - 1) / TB;
    int eB = (E + TB - 1) / TB;
    int NB1024 = (N + 1023) / 1024;
    int gw = (N * 32 + TB - 1) / TB;
    int gemmB = (N + 127) / 128;

    zero_kernel<<<nB, TB>>>(N);
    deg_kernel<<<eB, TB>>>(ei, E);
    scanp3_kernel<<<NB1024, 1024>>>(N);
    csr_fill_kernel<<<eB, TB>>>(ei, E);
    wprep_kernel<<<(NCONV * 2 * H * H + TB - 1) / TB, TB>>>(Wmid);
    inlayer_kernel<<<gw, TB>>>(x, Win, bin, N);

    for (int l = 0; l < 3; l++) {
        int c0 = 2 * l, c1 = 2 * l + 1;
        gather_kernel<<<gw, TB>>>(0, N);
        gemm_kernel<<<gemmB, TB>>>(c0, bmid + (size_t)c0 * H,
                                   Wmid + ((size_t)c0 * 129 + 128) * H, N, 0, 0);
        gather_kernel<<<gw, TB>>>(1, N);
        gemm_kernel<<<gemmB, TB>>>(c1, bmid + (size_t)c1 * H,
                                   Wmid + ((size_t)c1 * 129 + 128) * H, N, 1, 1);
    }

    dot_kernel<<<gw, TB>>>(Wout, N);
    final_kernel<<<nB, TB>>>(x, Wout, bout, out, N);
}

// round 9
// speedup vs baseline: 2.3641x; 1.2945x over previous
#include <cuda_runtime.h>
#include <cstdint>

#define NCAP 50176
#define ECAP 1700000
#define H 64
#define NCONV 6

// ---------------- static device scratch ----------------
__device__ unsigned long long g_pack[NCAP];     // hi32 = deg, lo32 = sum(sign)+deg*2^20
__device__ int    g_offs[NCAP + 1];
__device__ int    g_cursor[NCAP];
__device__ int    g_csr[ECAP];
__device__ float  g_inv[NCAP];
__device__ float  g_m[NCAP];
__device__ float  g_t[NCAP];
__device__ float  g_ya[NCAP];
__device__ float  g_yb[NCAP];
__device__ float4 g_nod[NCAP];                  // (A,B,C,T) per node
__device__ float4 g_SQ[NCAP];                   // neighbor sums of g_nod
__device__ float  g_buf1[(size_t)NCAP * H];
__device__ float  g_buf2[(size_t)NCAP * H];
__device__ float  g_G[(size_t)NCAP * 2 * H];
__device__ float  g_Wf[NCONV * 2 * H * H];      // MMA fragment-ordered weights
__device__ int    g_bsum[64];
__device__ int    g_bflag[64];

// tf32 round-to-nearest (unbiased); result reinterpretable as fp32
__device__ __forceinline__ float tf32r(float f) {
    uint32_t u;
    asm("cvt.rna.tf32.f32 %0, %1;" : "=r"(u) : "f"(f));
    return __uint_as_float(u);
}

// ---------------- preprocessing ----------------

__global__ void zero_kernel(int n) {
    int i = blockIdx.x * blockDim.x + threadIdx.x;
    if (i < n) g_pack[i] = 0ULL;
    if (i < 64) { g_bflag[i] = 0; g_bsum[i] = 0; }
}

__global__ void deg_kernel(const int* __restrict__ ei, int E) {
    int e = blockIdx.x * blockDim.x + threadIdx.x;
    if (e >= E) return;
    int s = ei[e];
    int d = ei[E + e];
    int sg = (s > d) ? 1 : ((s < d) ? -1 : 0);
    unsigned long long add = (1ULL << 32) | (unsigned int)(sg + (1 << 20));
    atomicAdd(&g_pack[d], add);
}

// merged scan + finalize with decoupled lookback (<=49 co-resident blocks)
__global__ void scanp3_kernel(int n) {
    __shared__ int sm[32];
    __shared__ int s_base;
    int tid = threadIdx.x;
    int lane = tid & 31, wid = tid >> 5;
    int b = blockIdx.x;
    int i = b * 1024 + tid;

    unsigned long long p = (i < n) ? g_pack[i] : 0ULL;
    int v = (int)(p >> 32);
    int incl = v;
#pragma unroll
    for (int o = 1; o < 32; o <<= 1) {
        int u = __shfl_up_sync(0xffffffffu, incl, o);
        if (lane >= o) incl += u;
    }
    if (lane == 31) sm[wid] = incl;
    __syncthreads();
    if (wid == 0) {
        int t = sm[lane];
#pragma unroll
        for (int o = 1; o < 32; o <<= 1) {
            int u = __shfl_up_sync(0xffffffffu, t, o);
            if (lane >= o) t += u;
        }
        sm[lane] = t;
    }
    __syncthreads();
    int wbase = (wid > 0) ? sm[wid - 1] : 0;
    int local_excl = wbase + incl - v;
    int block_total = sm[31];

    if (tid == 0) {
        atomicExch(&g_bsum[b], block_total);
        __threadfence();
        atomicExch(&g_bflag[b], 1);
    }
    if (tid < 32) {
        int base = 0;
        for (int q = tid; q < b; q += 32) {
            while (atomicAdd(&g_bflag[q], 0) == 0) { }
            base += atomicAdd(&g_bsum[q], 0);
        }
#pragma unroll
        for (int o = 16; o > 0; o >>= 1) base += __shfl_xor_sync(0xffffffffu, base, o);
        if (tid == 0) s_base = base;
    }
    __syncthreads();
    if (i >= n) return;
    int off = s_base + local_excl;
    g_offs[i] = off;
    g_cursor[i] = off;
    int d = v;
    int sgnsum = (int)(unsigned int)(p & 0xffffffffu) - (d << 20);
    float inv = 1.0f / fmaxf((float)d, 1.0f);
    g_inv[i] = inv;
    g_m[i] = d > 0 ? 1.0f : 0.0f;
    g_t[i] = inv * (float)sgnsum;
    if (i == n - 1) g_offs[n] = off + d;
}

__global__ void csr_fill_kernel(const int* __restrict__ ei, int E) {
    int e = blockIdx.x * blockDim.x + threadIdx.x;
    if (e >= E) return;
    int s = ei[e];
    int d = ei[E + e];
    int pos = atomicAdd(&g_cursor[d], 1);
    g_csr[pos] = s;
}

// Build fragment-ordered, tf32-rounded combined weights.
// Combined Wc[k][c]: k<64 -> W1-W2 (Wmid row k - row 64+k), k>=64 -> W2 (row k).
// Fragment layout: Wf[conv][kstep(16)][nt(8)][lane(32)][par(2)]
//   k = kstep*8 + (lane&3) + par*4 ; c = nt*8 + (lane>>2)
__global__ void wprep_kernel(const float* __restrict__ Wmid) {
    int idx = blockIdx.x * blockDim.x + threadIdx.x;
    if (idx >= NCONV * 2 * H * H) return;
    int conv = idx / 8192;
    int rem = idx % 8192;
    int kstep = rem / 512;
    int rem2 = rem % 512;
    int nt = rem2 / 64;
    int l2 = rem2 % 64;
    int lane = l2 >> 1;
    int par = l2 & 1;
    int k = kstep * 8 + (lane & 3) + par * 4;
    int c = nt * 8 + (lane >> 2);
    float v = Wmid[((size_t)conv * 129 + k) * H + c];
    if (k < H) v -= Wmid[((size_t)conv * 129 + H + k) * H + c];
    g_Wf[idx] = tf32r(v);
}

// ---------------- input layer, rank-4 form ----------------

// thread-per-node: scalar gather of x, pack per-node scalars (A,B,C,T)
__global__ void nodpack_kernel(const float* __restrict__ x, int n) {
    int i = blockIdx.x * blockDim.x + threadIdx.x;
    if (i >= n) return;
    int k = g_offs[i], e = g_offs[i + 1];
    float s0 = 0, s1 = 0, s2 = 0, s3 = 0;
    for (; k + 4 <= e; k += 4) {
        s0 += __ldg(&x[g_csr[k]]);
        s1 += __ldg(&x[g_csr[k + 1]]);
        s2 += __ldg(&x[g_csr[k + 2]]);
        s3 += __ldg(&x[g_csr[k + 3]]);
    }
    for (; k < e; ++k) s0 += __ldg(&x[g_csr[k]]);
    float Sx = (s0 + s1) + (s2 + s3);
    float m = g_m[i], inv = g_inv[i], t = g_t[i];
    g_nod[i] = make_float4(m * x[i], inv * Sx, m, t);
}

// thread-per-node: SQ_i = sum over neighbors of g_nod[j]
__global__ void quadgather_kernel(int n) {
    int i = blockIdx.x * blockDim.x + threadIdx.x;
    if (i >= n) return;
    int k = g_offs[i], e = g_offs[i + 1];
    float4 a0 = make_float4(0.f, 0.f, 0.f, 0.f), a1 = a0, a2 = a0, a3 = a0;
    for (; k + 4 <= e; k += 4) {
        float4 v0 = g_nod[g_csr[k]];
        float4 v1 = g_nod[g_csr[k + 1]];
        float4 v2 = g_nod[g_csr[k + 2]];
        float4 v3 = g_nod[g_csr[k + 3]];
        a0.x += v0.x; a0.y += v0.y; a0.z += v0.z; a0.w += v0.w;
        a1.x += v1.x; a1.y += v1.y; a1.z += v1.z; a1.w += v1.w;
        a2.x += v2.x; a2.y += v2.y; a2.z += v2.z; a2.w += v2.w;
        a3.x += v3.x; a3.y += v3.y; a3.z += v3.z; a3.w += v3.w;
    }
    for (; k < e; ++k) {
        float4 v = g_nod[g_csr[k]];
        a0.x += v.x; a0.y += v.y; a0.z += v.z; a0.w += v.w;
    }
    g_SQ[i] = make_float4((a0.x + a1.x) + (a2.x + a3.x),
                          (a0.y + a1.y) + (a2.y + a3.y),
                          (a0.z + a1.z) + (a2.z + a3.z),
                          (a0.w + a1.w) + (a2.w + a3.w));
}

// warp-per-node: build buf2 row (fp32) and conv0's G row (tf32-rounded)
__global__ void inG_kernel(const float* __restrict__ Win,
                           const float* __restrict__ bin, int n) {
    int warp = (blockIdx.x * blockDim.x + threadIdx.x) >> 5;
    int lane = threadIdx.x & 31;
    if (warp >= n) return;
    float4 nd = g_nod[warp];
    float4 sq = g_SQ[warp];
    float m = g_m[warp], inv = g_inv[warp];
    int c0 = 2 * lane;
    float2 w1 = *(const float2*)(Win + c0);
    float2 w2 = *(const float2*)(Win + H + c0);
    float2 w3 = *(const float2*)(Win + 2 * H + c0);
    float2 b  = *(const float2*)(bin + c0);
    float2 d1 = make_float2(w1.x - w2.x, w1.y - w2.y);
    float2 xv;
    xv.x = nd.x * d1.x + nd.z * b.x + nd.y * w2.x + nd.w * w3.x;
    xv.y = nd.x * d1.y + nd.z * b.y + nd.y * w2.y + nd.w * w3.y;
    *(float2*)(g_buf2 + (size_t)warp * H + c0) = xv;
    float2 gv;
    gv.x = inv * (sq.x * d1.x + sq.z * b.x + sq.y * w2.x + sq.w * w3.x);
    gv.y = inv * (sq.x * d1.y + sq.z * b.y + sq.y * w2.y + sq.w * w3.y);
    float* Gr = g_G + (size_t)warp * (2 * H);
    *(float2*)(Gr + c0) = make_float2(tf32r(m * xv.x), tf32r(m * xv.y));
    *(float2*)(Gr + H + c0) = make_float2(tf32r(gv.x), tf32r(gv.y));
}

// ---------------- mid layers: paired-edge float4 gather (tf32-rounded G) ----------------

__global__ void gather_kernel(int sel, int n) {
    int warp = (blockIdx.x * blockDim.x + threadIdx.x) >> 5;
    int lane = threadIdx.x & 31;
    if (warp >= n) return;
    const float4* X4 = (const float4*)(sel ? g_buf1 : g_buf2);
    int hl = lane & 15;
    int par = lane >> 4;
    int k = g_offs[warp], e = g_offs[warp + 1];
    float4 a0 = make_float4(0.f, 0.f, 0.f, 0.f), a1 = a0;
    for (; k + 8 <= e; k += 8) {
        int j0 = g_csr[k + par];
        int j1 = g_csr[k + 2 + par];
        int j2 = g_csr[k + 4 + par];
        int j3 = g_csr[k + 6 + par];
        float4 v0 = X4[(size_t)j0 * 16 + hl];
        float4 v1 = X4[(size_t)j1 * 16 + hl];
        float4 v2 = X4[(size_t)j2 * 16 + hl];
        float4 v3 = X4[(size_t)j3 * 16 + hl];
        a0.x += v0.x; a0.y += v0.y; a0.z += v0.z; a0.w += v0.w;
        a1.x += v1.x; a1.y += v1.y; a1.z += v1.z; a1.w += v1.w;
        a0.x += v2.x; a0.y += v2.y; a0.z += v2.z; a0.w += v2.w;
        a1.x += v3.x; a1.y += v3.y; a1.z += v3.z; a1.w += v3.w;
    }
    for (; k + 2 <= e; k += 2) {
        int j = g_csr[k + par];
        float4 v = X4[(size_t)j * 16 + hl];
        a0.x += v.x; a0.y += v.y; a0.z += v.z; a0.w += v.w;
    }
    if (k < e && par == 0) {
        int j = g_csr[k];
        float4 v = X4[(size_t)j * 16 + hl];
        a1.x += v.x; a1.y += v.y; a1.z += v.z; a1.w += v.w;
    }
    float4 s;
    s.x = a0.x + a1.x; s.y = a0.y + a1.y; s.z = a0.z + a1.z; s.w = a0.w + a1.w;
    s.x += __shfl_xor_sync(0xffffffffu, s.x, 16);
    s.y += __shfl_xor_sync(0xffffffffu, s.y, 16);
    s.z += __shfl_xor_sync(0xffffffffu, s.z, 16);
    s.w += __shfl_xor_sync(0xffffffffu, s.w, 16);
    float m = g_m[warp], inv = g_inv[warp];
    float4* Gr = (float4*)(g_G + (size_t)warp * (2 * H));
    if (par == 0) {
        float4 xi = X4[(size_t)warp * 16 + hl];
        Gr[hl] = make_float4(tf32r(m * xi.x), tf32r(m * xi.y),
                             tf32r(m * xi.z), tf32r(m * xi.w));
    } else {
        Gr[16 + hl] = make_float4(tf32r(inv * s.x), tf32r(inv * s.y),
                                  tf32r(inv * s.z), tf32r(inv * s.w));
    }
}

// ---------------- mid layers: tf32 tensor-core GEMM ----------------

__device__ __forceinline__ void mma_tf32(float& d0, float& d1, float& d2, float& d3,
                                         uint32_t a0, uint32_t a1, uint32_t a2, uint32_t a3,
                                         uint32_t b0, uint32_t b1) {
    asm volatile(
        "mma.sync.aligned.m16n8k8.row.col.f32.tf32.tf32.f32 "
        "{%0,%1,%2,%3}, {%4,%5,%6,%7}, {%8,%9}, {%0,%1,%2,%3};"
        : "+f"(d0), "+f"(d1), "+f"(d2), "+f"(d3)
        : "r"(a0), "r"(a1), "r"(a2), "r"(a3), "r"(b0), "r"(b1));
}

__global__ void __launch_bounds__(256) gemm_kernel(
    int conv, const float* __restrict__ bias, const float* __restrict__ wsgn,
    int n, int out_sel, int res_flag) {
    __shared__ float Ws[2 * H * H];         // fragment-ordered weights, 32 KB
    int tid = threadIdx.x;
    const float4* Wsrc = (const float4*)(g_Wf + (size_t)conv * (2 * H * H));
    float4* Wdst = (float4*)Ws;
#pragma unroll
    for (int r = 0; r < 8; r++) Wdst[r * 256 + tid] = __ldg(&Wsrc[r * 256 + tid]);
    __syncthreads();

    int w = tid >> 5, lane = tid & 31;
    int tig = lane & 3, gid = lane >> 2;
    int rbase = blockIdx.x * 128 + w * 16;

    float acc[8][4];
#pragma unroll
    for (int nt = 0; nt < 8; nt++)
#pragma unroll
        for (int j = 0; j < 4; j++) acc[nt][j] = 0.f;

    const uint32_t* Gu = (const uint32_t*)g_G;
    const float2* Wf2 = (const float2*)Ws;  // idx = (kstep*8 + nt)*32 + lane

#pragma unroll 4
    for (int kstep = 0; kstep < 16; kstep++) {
        int kk = kstep * 8;
        uint32_t a0 = __ldg(&Gu[(size_t)(rbase + gid) * 128 + kk + tig]);
        uint32_t a1 = __ldg(&Gu[(size_t)(rbase + gid + 8) * 128 + kk + tig]);
        uint32_t a2 = __ldg(&Gu[(size_t)(rbase + gid) * 128 + kk + tig + 4]);
        uint32_t a3 = __ldg(&Gu[(size_t)(rbase + gid + 8) * 128 + kk + tig + 4]);
#pragma unroll
        for (int nt = 0; nt < 8; nt++) {
            float2 bb = Wf2[(kstep * 8 + nt) * 32 + lane];
            mma_tf32(acc[nt][0], acc[nt][1], acc[nt][2], acc[nt][3],
                     a0, a1, a2, a3,
                     __float_as_uint(bb.x), __float_as_uint(bb.y));
        }
    }

    // epilogue: thread owns rows rbase+gid, rbase+gid+8; cols nt*8 + 2*tig, +1
    float* out = out_sel ? g_buf2 : g_buf1;
#pragma unroll
    for (int h = 0; h < 2; h++) {
        int r = rbase + gid + 8 * h;
        if (r >= n) continue;
        float m = g_m[r], t = g_t[r];
#pragma unroll
        for (int nt = 0; nt < 8; nt++) {
            int c = nt * 8 + 2 * tig;
            float o0 = acc[nt][2 * h]     + m * __ldg(&bias[c])     + t * __ldg(&wsgn[c]);
            float o1 = acc[nt][2 * h + 1] + m * __ldg(&bias[c + 1]) + t * __ldg(&wsgn[c + 1]);
            if (res_flag) {
                float2 rv = *(const float2*)(g_buf2 + (size_t)r * H + c);
                o0 += rv.x; o1 += rv.y;
            }
            o0 = o0 > 0.f ? o0 : 0.01f * o0;
            o1 = o1 > 0.f ? o1 : 0.01f * o1;
            *(float2*)(out + (size_t)r * H + c) = make_float2(o0, o1);
        }
    }
}

// ---------------- output layer ----------------

__global__ void dot_kernel(const float* __restrict__ Wout, int n) {
    int warp = (blockIdx.x * blockDim.x + threadIdx.x) >> 5;
    int lane = threadIdx.x & 31;
    if (warp >= n) return;
    const float2* X = (const float2*)g_buf2;
    float2 v = X[warp * 32 + lane];
    int c0 = 2 * lane, c1 = c0 + 1;
    float b0 = Wout[H + c0], b1 = Wout[H + c1];
    float a0 = Wout[c0] - b0, a1 = Wout[c1] - b1;
    float pa = v.x * a0 + v.y * a1;
    float pb = v.x * b0 + v.y * b1;
#pragma unroll
    for (int o = 16; o > 0; o >>= 1) {
        pa += __shfl_xor_sync(0xffffffffu, pa, o);
        pb += __shfl_xor_sync(0xffffffffu, pb, o);
    }
    if (lane == 0) { g_ya[warp] = pa; g_yb[warp] = pb; }
}

__global__ void final_kernel(const float* __restrict__ x, const float* __restrict__ Wout,
                             const float* __restrict__ bout, float* __restrict__ out, int n) {
    int i = blockIdx.x * blockDim.x + threadIdx.x;
    if (i >= n) return;
    int k = g_offs[i], e = g_offs[i + 1];
    float s0 = 0, s1 = 0, s2 = 0, s3 = 0;
    for (; k + 4 <= e; k += 4) {
        s0 += g_yb[g_csr[k]];
        s1 += g_yb[g_csr[k + 1]];
        s2 += g_yb[g_csr[k + 2]];
        s3 += g_yb[g_csr[k + 3]];
    }
    for (; k < e; ++k) s0 += g_yb[g_csr[k]];
    float S = (s0 + s1) + (s2 + s3);
    out[i] = g_m[i] * (g_ya[i] + bout[0]) + g_inv[i] * S + g_t[i] * Wout[2 * H] + x[i];
}

// ---------------- launch ----------------

extern "C" void kernel_launch(void* const* d_in, const int* in_sizes, int n_in,
                              void* d_out, int out_size) {
    const float* x    = (const float*)d_in[0];
    const int*   ei   = (const int*)d_in[1];
    const float* Win  = (const float*)d_in[2];
    const float* bin  = (const float*)d_in[3];
    const float* Wmid = (const float*)d_in[4];
    const float* bmid = (const float*)d_in[5];
    const float* Wout = (const float*)d_in[6];
    const float* bout = (const float*)d_in[7];
    int N = in_sizes[0];
    int E = in_sizes[1] / 2;
    float* out = (float*)d_out;

    const int TB = 256;
    int nB = (N + TB - 1) / TB;
    int eB = (E + TB - 1) / TB;
    int NB1024 = (N + 1023) / 1024;
    int gw = (N * 32 + TB - 1) / TB;
    int gemmB = (N + 127) / 128;

    zero_kernel<<<nB, TB>>>(N);
    deg_kernel<<<eB, TB>>>(ei, E);
    scanp3_kernel<<<NB1024, 1024>>>(N);
    csr_fill_kernel<<<eB, TB>>>(ei, E);
    wprep_kernel<<<(NCONV * 2 * H * H + TB - 1) / TB, TB>>>(Wmid);

    // input layer + conv0 G via rank-4 scalar gathers
    nodpack_kernel<<<nB, TB>>>(x, N);
    quadgather_kernel<<<nB, TB>>>(N);
    inG_kernel<<<gw, TB>>>(Win, bin, N);
    gemm_kernel<<<gemmB, TB>>>(0, bmid, Wmid + 128 * H, N, 0, 0);        // -> buf1

    // conv1..conv5 with wide gathers
    gather_kernel<<<gw, TB>>>(1, N);                                      // buf1 -> G
    gemm_kernel<<<gemmB, TB>>>(1, bmid + (size_t)1 * H,
                               Wmid + ((size_t)1 * 129 + 128) * H, N, 1, 1); // -> buf2 (+res)
    for (int l = 1; l < 3; l++) {
        int c0 = 2 * l, c1 = 2 * l + 1;
        gather_kernel<<<gw, TB>>>(0, N);                                  // buf2 -> G
        gemm_kernel<<<gemmB, TB>>>(c0, bmid + (size_t)c0 * H,
                                   Wmid + ((size_t)c0 * 129 + 128) * H, N, 0, 0);
        gather_kernel<<<gw, TB>>>(1, N);                                  // buf1 -> G
        gemm_kernel<<<gemmB, TB>>>(c1, bmid + (size_t)c1 * H,
                                   Wmid + ((size_t)c1 * 129 + 128) * H, N, 1, 1);
    }

    dot_kernel<<<gw, TB>>>(Wout, N);
    final_kernel<<<nB, TB>>>(x, Wout, bout, out, N);
}

// round 12
// speedup vs baseline: 2.4053x; 1.0175x over previous
#include <cuda_runtime.h>
#include <cuda_fp16.h>
#include <cstdint>

#define NCAP 50176
#define ECAP 1700000
#define H 64
#define NCONV 6

// ---------------- static device scratch ----------------
__device__ unsigned long long g_pack[NCAP];     // hi32 = deg, lo32 = sum(sign)+deg*2^20
__device__ int    g_offs[NCAP + 1];
__device__ int    g_cursor[NCAP];
__device__ int    g_csr[ECAP];
__device__ float  g_inv[NCAP];
__device__ float  g_m[NCAP];
__device__ float  g_t[NCAP];
__device__ float  g_ya[NCAP];
__device__ float  g_yb[NCAP];
__device__ float4 g_nod[NCAP];                  // (A,B,C,T) per node
__device__ float4 g_SQ[NCAP];                   // neighbor sums of g_nod
__device__ float  g_buf1[(size_t)NCAP * H];
__device__ float  g_buf2[(size_t)NCAP * H];
__device__ __half2 g_h[(size_t)NCAP * (H / 2)]; // fp16 copy of latest conv output
__device__ float  g_G[(size_t)NCAP * 2 * H];
__device__ float  g_Wf[NCONV * 2 * H * H];      // MMA fragment-ordered weights
__device__ int    g_bsum[64];
__device__ int    g_bflag[64];

// tf32 round-to-nearest (unbiased); result reinterpretable as fp32
__device__ __forceinline__ float tf32r(float f) {
    uint32_t u;
    asm("cvt.rna.tf32.f32 %0, %1;" : "=r"(u) : "f"(f));
    return __uint_as_float(u);
}

// ---------------- preprocessing ----------------

__global__ void zero_kernel(int n) {
    int i = blockIdx.x * blockDim.x + threadIdx.x;
    if (i < n) g_pack[i] = 0ULL;
    if (i < 64) { g_bflag[i] = 0; g_bsum[i] = 0; }
}

__global__ void deg_kernel(const int* __restrict__ ei, int E) {
    int e = blockIdx.x * blockDim.x + threadIdx.x;
    if (e >= E) return;
    int s = ei[e];
    int d = ei[E + e];
    int sg = (s > d) ? 1 : ((s < d) ? -1 : 0);
    unsigned long long add = (1ULL << 32) | (unsigned int)(sg + (1 << 20));
    atomicAdd(&g_pack[d], add);
}

// merged scan + finalize with decoupled lookback (<=49 co-resident blocks)
__global__ void scanp3_kernel(int n) {
    __shared__ int sm[32];
    __shared__ int s_base;
    int tid = threadIdx.x;
    int lane = tid & 31, wid = tid >> 5;
    int b = blockIdx.x;
    int i = b * 1024 + tid;

    unsigned long long p = (i < n) ? g_pack[i] : 0ULL;
    int v = (int)(p >> 32);
    int incl = v;
#pragma unroll
    for (int o = 1; o < 32; o <<= 1) {
        int u = __shfl_up_sync(0xffffffffu, incl, o);
        if (lane >= o) incl += u;
    }
    if (lane == 31) sm[wid] = incl;
    __syncthreads();
    if (wid == 0) {
        int t = sm[lane];
#pragma unroll
        for (int o = 1; o < 32; o <<= 1) {
            int u = __shfl_up_sync(0xffffffffu, t, o);
            if (lane >= o) t += u;
        }
        sm[lane] = t;
    }
    __syncthreads();
    int wbase = (wid > 0) ? sm[wid - 1] : 0;
    int local_excl = wbase + incl - v;
    int block_total = sm[31];

    if (tid == 0) {
        atomicExch(&g_bsum[b], block_total);
        __threadfence();
        atomicExch(&g_bflag[b], 1);
    }
    if (tid < 32) {
        int base = 0;
        for (int q = tid; q < b; q += 32) {
            while (atomicAdd(&g_bflag[q], 0) == 0) { }
            base += atomicAdd(&g_bsum[q], 0);
        }
#pragma unroll
        for (int o = 16; o > 0; o >>= 1) base += __shfl_xor_sync(0xffffffffu, base, o);
        if (tid == 0) s_base = base;
    }
    __syncthreads();
    if (i >= n) return;
    int off = s_base + local_excl;
    g_offs[i] = off;
    g_cursor[i] = off;
    int d = v;
    int sgnsum = (int)(unsigned int)(p & 0xffffffffu) - (d << 20);
    float inv = 1.0f / fmaxf((float)d, 1.0f);
    g_inv[i] = inv;
    g_m[i] = d > 0 ? 1.0f : 0.0f;
    g_t[i] = inv * (float)sgnsum;
    if (i == n - 1) g_offs[n] = off + d;
}

__global__ void csr_fill_kernel(const int* __restrict__ ei, int E) {
    int e = blockIdx.x * blockDim.x + threadIdx.x;
    if (e >= E) return;
    int s = ei[e];
    int d = ei[E + e];
    int pos = atomicAdd(&g_cursor[d], 1);
    g_csr[pos] = s;
}

// Build fragment-ordered, tf32-rounded combined weights.
// Combined Wc[k][c]: k<64 -> W1-W2 (Wmid row k - row 64+k), k>=64 -> W2 (row k).
// Fragment layout: Wf[conv][kstep(16)][nt(8)][lane(32)][par(2)]
//   k = kstep*8 + (lane&3) + par*4 ; c = nt*8 + (lane>>2)
__global__ void wprep_kernel(const float* __restrict__ Wmid) {
    int idx = blockIdx.x * blockDim.x + threadIdx.x;
    if (idx >= NCONV * 2 * H * H) return;
    int conv = idx / 8192;
    int rem = idx % 8192;
    int kstep = rem / 512;
    int rem2 = rem % 512;
    int nt = rem2 / 64;
    int l2 = rem2 % 64;
    int lane = l2 >> 1;
    int par = l2 & 1;
    int k = kstep * 8 + (lane & 3) + par * 4;
    int c = nt * 8 + (lane >> 2);
    float v = Wmid[((size_t)conv * 129 + k) * H + c];
    if (k < H) v -= Wmid[((size_t)conv * 129 + H + k) * H + c];
    g_Wf[idx] = tf32r(v);
}

// ---------------- input layer, rank-4 form ----------------

__global__ void nodpack_kernel(const float* __restrict__ x, int n) {
    int i = blockIdx.x * blockDim.x + threadIdx.x;
    if (i >= n) return;
    int k = g_offs[i], e = g_offs[i + 1];
    float s0 = 0, s1 = 0, s2 = 0, s3 = 0;
    for (; k + 4 <= e; k += 4) {
        s0 += __ldg(&x[g_csr[k]]);
        s1 += __ldg(&x[g_csr[k + 1]]);
        s2 += __ldg(&x[g_csr[k + 2]]);
        s3 += __ldg(&x[g_csr[k + 3]]);
    }
    for (; k < e; ++k) s0 += __ldg(&x[g_csr[k]]);
    float Sx = (s0 + s1) + (s2 + s3);
    float m = g_m[i], inv = g_inv[i], t = g_t[i];
    g_nod[i] = make_float4(m * x[i], inv * Sx, m, t);
}

__global__ void quadgather_kernel(int n) {
    int i = blockIdx.x * blockDim.x + threadIdx.x;
    if (i >= n) return;
    int k = g_offs[i], e = g_offs[i + 1];
    float4 a0 = make_float4(0.f, 0.f, 0.f, 0.f), a1 = a0, a2 = a0, a3 = a0;
    for (; k + 4 <= e; k += 4) {
        float4 v0 = g_nod[g_csr[k]];
        float4 v1 = g_nod[g_csr[k + 1]];
        float4 v2 = g_nod[g_csr[k + 2]];
        float4 v3 = g_nod[g_csr[k + 3]];
        a0.x += v0.x; a0.y += v0.y; a0.z += v0.z; a0.w += v0.w;
        a1.x += v1.x; a1.y += v1.y; a1.z += v1.z; a1.w += v1.w;
        a2.x += v2.x; a2.y += v2.y; a2.z += v2.z; a2.w += v2.w;
        a3.x += v3.x; a3.y += v3.y; a3.z += v3.z; a3.w += v3.w;
    }
    for (; k < e; ++k) {
        float4 v = g_nod[g_csr[k]];
        a0.x += v.x; a0.y += v.y; a0.z += v.z; a0.w += v.w;
    }
    g_SQ[i] = make_float4((a0.x + a1.x) + (a2.x + a3.x),
                          (a0.y + a1.y) + (a2.y + a3.y),
                          (a0.z + a1.z) + (a2.z + a3.z),
                          (a0.w + a1.w) + (a2.w + a3.w));
}

// warp-per-node: build buf2 row (fp32) and conv0's G row (tf32-rounded)
__global__ void inG_kernel(const float* __restrict__ Win,
                           const float* __restrict__ bin, int n) {
    int warp = (blockIdx.x * blockDim.x + threadIdx.x) >> 5;
    int lane = threadIdx.x & 31;
    if (warp >= n) return;
    float4 nd = g_nod[warp];
    float4 sq = g_SQ[warp];
    float m = g_m[warp], inv = g_inv[warp];
    int c0 = 2 * lane;
    float2 w1 = *(const float2*)(Win + c0);
    float2 w2 = *(const float2*)(Win + H + c0);
    float2 w3 = *(const float2*)(Win + 2 * H + c0);
    float2 b  = *(const float2*)(bin + c0);
    float2 d1 = make_float2(w1.x - w2.x, w1.y - w2.y);
    float2 xv;
    xv.x = nd.x * d1.x + nd.z * b.x + nd.y * w2.x + nd.w * w3.x;
    xv.y = nd.x * d1.y + nd.z * b.y + nd.y * w2.y + nd.w * w3.y;
    *(float2*)(g_buf2 + (size_t)warp * H + c0) = xv;
    float2 gv;
    gv.x = inv * (sq.x * d1.x + sq.z * b.x + sq.y * w2.x + sq.w * w3.x);
    gv.y = inv * (sq.x * d1.y + sq.z * b.y + sq.y * w2.y + sq.w * w3.y);
    float* Gr = g_G + (size_t)warp * (2 * H);
    *(float2*)(Gr + c0) = make_float2(tf32r(m * xv.x), tf32r(m * xv.y));
    *(float2*)(Gr + H + c0) = make_float2(tf32r(gv.x), tf32r(gv.y));
}

// ---------------- mid layers: paired-edge fp16 gather ----------------
// Half-warp per edge; each lane loads uint2 (8B = 4 fp16), 16 lanes = full
// 128B row = half the L2 sectors of the fp32 version. fp32 accumulate;
// x_i path read fp32 from buf; G written tf32.

__global__ void gather_kernel(int sel, int n) {
    int warp = (blockIdx.x * blockDim.x + threadIdx.x) >> 5;
    int lane = threadIdx.x & 31;
    if (warp >= n) return;
    const float4* X4 = (const float4*)(sel ? g_buf1 : g_buf2);
    const uint2* Xh = (const uint2*)g_h;     // row j: 16 uint2
    int hl = lane & 15;
    int par = lane >> 4;
    int k = g_offs[warp], e = g_offs[warp + 1];
    float4 a0 = make_float4(0.f, 0.f, 0.f, 0.f), a1 = a0;
    for (; k + 8 <= e; k += 8) {
        int j0 = g_csr[k + par];
        int j1 = g_csr[k + 2 + par];
        int j2 = g_csr[k + 4 + par];
        int j3 = g_csr[k + 6 + par];
        uint2 u0 = Xh[(size_t)j0 * 16 + hl];
        uint2 u1 = Xh[(size_t)j1 * 16 + hl];
        uint2 u2 = Xh[(size_t)j2 * 16 + hl];
        uint2 u3 = Xh[(size_t)j3 * 16 + hl];
        float2 p0 = __half22float2(*(__half2*)&u0.x), q0 = __half22float2(*(__half2*)&u0.y);
        float2 p1 = __half22float2(*(__half2*)&u1.x), q1 = __half22float2(*(__half2*)&u1.y);
        float2 p2 = __half22float2(*(__half2*)&u2.x), q2 = __half22float2(*(__half2*)&u2.y);
        float2 p3 = __half22float2(*(__half2*)&u3.x), q3 = __half22float2(*(__half2*)&u3.y);
        a0.x += p0.x; a0.y += p0.y; a0.z += q0.x; a0.w += q0.y;
        a1.x += p1.x; a1.y += p1.y; a1.z += q1.x; a1.w += q1.y;
        a0.x += p2.x; a0.y += p2.y; a0.z += q2.x; a0.w += q2.y;
        a1.x += p3.x; a1.y += p3.y; a1.z += q3.x; a1.w += q3.y;
    }
    for (; k + 2 <= e; k += 2) {
        int j = g_csr[k + par];
        uint2 u = Xh[(size_t)j * 16 + hl];
        float2 p = __half22float2(*(__half2*)&u.x), q = __half22float2(*(__half2*)&u.y);
        a0.x += p.x; a0.y += p.y; a0.z += q.x; a0.w += q.y;
    }
    if (k < e && par == 0) {                 // last odd edge: lanes 0-15 only
        int j = g_csr[k];
        uint2 u = Xh[(size_t)j * 16 + hl];
        float2 p = __half22float2(*(__half2*)&u.x), q = __half22float2(*(__half2*)&u.y);
        a1.x += p.x; a1.y += p.y; a1.z += q.x; a1.w += q.y;
    }
    float4 s;
    s.x = a0.x + a1.x; s.y = a0.y + a1.y; s.z = a0.z + a1.z; s.w = a0.w + a1.w;
    s.x += __shfl_xor_sync(0xffffffffu, s.x, 16);
    s.y += __shfl_xor_sync(0xffffffffu, s.y, 16);
    s.z += __shfl_xor_sync(0xffffffffu, s.z, 16);
    s.w += __shfl_xor_sync(0xffffffffu, s.w, 16);
    float m = g_m[warp], inv = g_inv[warp];
    float4* Gr = (float4*)(g_G + (size_t)warp * (2 * H));
    if (par == 0) {
        float4 xi = X4[(size_t)warp * 16 + hl];
        Gr[hl] = make_float4(tf32r(m * xi.x), tf32r(m * xi.y),
                             tf32r(m * xi.z), tf32r(m * xi.w));
    } else {
        Gr[16 + hl] = make_float4(tf32r(inv * s.x), tf32r(inv * s.y),
                                  tf32r(inv * s.z), tf32r(inv * s.w));
    }
}

// ---------------- mid layers: tf32 tensor-core GEMM ----------------

__device__ __forceinline__ void mma_tf32(float& d0, float& d1, float& d2, float& d3,
                                         uint32_t a0, uint32_t a1, uint32_t a2, uint32_t a3,
                                         uint32_t b0, uint32_t b1) {
    asm volatile(
        "mma.sync.aligned.m16n8k8.row.col.f32.tf32.tf32.f32 "
        "{%0,%1,%2,%3}, {%4,%5,%6,%7}, {%8,%9}, {%0,%1,%2,%3};"
        : "+f"(d0), "+f"(d1), "+f"(d2), "+f"(d3)
        : "r"(a0), "r"(a1), "r"(a2), "r"(a3), "r"(b0), "r"(b1));
}

__global__ void __launch_bounds__(256) gemm_kernel(
    int conv, const float* __restrict__ bias, const float* __restrict__ wsgn,
    int n, int out_sel, int res_flag, int h_flag) {
    __shared__ float Ws[2 * H * H];         // fragment-ordered weights, 32 KB
    int tid = threadIdx.x;
    const float4* Wsrc = (const float4*)(g_Wf + (size_t)conv * (2 * H * H));
    float4* Wdst = (float4*)Ws;
#pragma unroll
    for (int r = 0; r < 8; r++) Wdst[r * 256 + tid] = __ldg(&Wsrc[r * 256 + tid]);
    __syncthreads();

    int w = tid >> 5, lane = tid & 31;
    int tig = lane & 3, gid = lane >> 2;
    int rbase = blockIdx.x * 128 + w * 16;

    float acc[8][4];
#pragma unroll
    for (int nt = 0; nt < 8; nt++)
#pragma unroll
        for (int j = 0; j < 4; j++) acc[nt][j] = 0.f;

    const uint32_t* Gu = (const uint32_t*)g_G;
    const float2* Wf2 = (const float2*)Ws;  // idx = (kstep*8 + nt)*32 + lane

#pragma unroll 4
    for (int kstep = 0; kstep < 16; kstep++) {
        int kk = kstep * 8;
        uint32_t a0 = __ldg(&Gu[(size_t)(rbase + gid) * 128 + kk + tig]);
        uint32_t a1 = __ldg(&Gu[(size_t)(rbase + gid + 8) * 128 + kk + tig]);
        uint32_t a2 = __ldg(&Gu[(size_t)(rbase + gid) * 128 + kk + tig + 4]);
        uint32_t a3 = __ldg(&Gu[(size_t)(rbase + gid + 8) * 128 + kk + tig + 4]);
#pragma unroll
        for (int nt = 0; nt < 8; nt++) {
            float2 bb = Wf2[(kstep * 8 + nt) * 32 + lane];
            mma_tf32(acc[nt][0], acc[nt][1], acc[nt][2], acc[nt][3],
                     a0, a1, a2, a3,
                     __float_as_uint(bb.x), __float_as_uint(bb.y));
        }
    }

    // epilogue: thread owns rows rbase+gid, rbase+gid+8; cols nt*8 + 2*tig, +1
    float* out = out_sel ? g_buf2 : g_buf1;
#pragma unroll
    for (int h = 0; h < 2; h++) {
        int r = rbase + gid + 8 * h;
        if (r >= n) continue;
        float m = g_m[r], t = g_t[r];
#pragma unroll
        for (int nt = 0; nt < 8; nt++) {
            int c = nt * 8 + 2 * tig;
            float o0 = acc[nt][2 * h]     + m * __ldg(&bias[c])     + t * __ldg(&wsgn[c]);
            float o1 = acc[nt][2 * h + 1] + m * __ldg(&bias[c + 1]) + t * __ldg(&wsgn[c + 1]);
            if (res_flag) {
                float2 rv = *(const float2*)(g_buf2 + (size_t)r * H + c);
                o0 += rv.x; o1 += rv.y;
            }
            o0 = o0 > 0.f ? o0 : 0.01f * o0;
            o1 = o1 > 0.f ? o1 : 0.01f * o1;
            *(float2*)(out + (size_t)r * H + c) = make_float2(o0, o1);
            if (h_flag)
                g_h[(size_t)r * 32 + (c >> 1)] = __floats2half2_rn(o0, o1);
        }
    }
}

// ---------------- output layer ----------------

__global__ void dot_kernel(const float* __restrict__ Wout, int n) {
    int warp = (blockIdx.x * blockDim.x + threadIdx.x) >> 5;
    int lane = threadIdx.x & 31;
    if (warp >= n) return;
    const float2* X = (const float2*)g_buf2;
    float2 v = X[warp * 32 + lane];
    int c0 = 2 * lane, c1 = c0 + 1;
    float b0 = Wout[H + c0], b1 = Wout[H + c1];
    float a0 = Wout[c0] - b0, a1 = Wout[c1] - b1;
    float pa = v.x * a0 + v.y * a1;
    float pb = v.x * b0 + v.y * b1;
#pragma unroll
    for (int o = 16; o > 0; o >>= 1) {
        pa += __shfl_xor_sync(0xffffffffu, pa, o);
        pb += __shfl_xor_sync(0xffffffffu, pb, o);
    }
    if (lane == 0) { g_ya[warp] = pa; g_yb[warp] = pb; }
}

__global__ void final_kernel(const float* __restrict__ x, const float* __restrict__ Wout,
                             const float* __restrict__ bout, float* __restrict__ out, int n) {
    int i = blockIdx.x * blockDim.x + threadIdx.x;
    if (i >= n) return;
    int k = g_offs[i], e = g_offs[i + 1];
    float s0 = 0, s1 = 0, s2 = 0, s3 = 0;
    for (; k + 4 <= e; k += 4) {
        s0 += g_yb[g_csr[k]];
        s1 += g_yb[g_csr[k + 1]];
        s2 += g_yb[g_csr[k + 2]];
        s3 += g_yb[g_csr[k + 3]];
    }
    for (; k < e; ++k) s0 += g_yb[g_csr[k]];
    float S = (s0 + s1) + (s2 + s3);
    out[i] = g_m[i] * (g_ya[i] + bout[0]) + g_inv[i] * S + g_t[i] * Wout[2 * H] + x[i];
}

// ---------------- launch ----------------

extern "C" void kernel_launch(void* const* d_in, const int* in_sizes, int n_in,
                              void* d_out, int out_size) {
    const float* x    = (const float*)d_in[0];
    const int*   ei   = (const int*)d_in[1];
    const float* Win  = (const float*)d_in[2];
    const float* bin  = (const float*)d_in[3];
    const float* Wmid = (const float*)d_in[4];
    const float* bmid = (const float*)d_in[5];
    const float* Wout = (const float*)d_in[6];
    const float* bout = (const float*)d_in[7];
    int N = in_sizes[0];
    int E = in_sizes[1] / 2;
    float* out = (float*)d_out;

    const int TB = 256;
    int nB = (N + TB - 1) / TB;
    int eB = (E + TB - 1) / TB;
    int NB1024 = (N + 1023) / 1024;
    int gw = (N * 32 + TB - 1) / TB;
    int gemmB = (N + 127) / 128;

    zero_kernel<<<nB, TB>>>(N);
    deg_kernel<<<eB, TB>>>(ei, E);
    scanp3_kernel<<<NB1024, 1024>>>(N);
    csr_fill_kernel<<<eB, TB>>>(ei, E);
    wprep_kernel<<<(NCONV * 2 * H * H + TB - 1) / TB, TB>>>(Wmid);

    // input layer + conv0 G via rank-4 scalar gathers
    nodpack_kernel<<<nB, TB>>>(x, N);
    quadgather_kernel<<<nB, TB>>>(N);
    inG_kernel<<<gw, TB>>>(Win, bin, N);
    gemm_kernel<<<gemmB, TB>>>(0, bmid, Wmid + 128 * H, N, 0, 0, 1);     // -> buf1 + g_h

    // conv1..conv5 with fp16-payload wide gathers
    gather_kernel<<<gw, TB>>>(1, N);                                      // g_h(+buf1) -> G
    gemm_kernel<<<gemmB, TB>>>(1, bmid + (size_t)1 * H,
                               Wmid + ((size_t)1 * 129 + 128) * H, N, 1, 1, 1); // -> buf2 + g_h
    for (int l = 1; l < 3; l++) {
        int c0 = 2 * l, c1 = 2 * l + 1;
        gather_kernel<<<gw, TB>>>(0, N);                                  // g_h(+buf2) -> G
        gemm_kernel<<<gemmB, TB>>>(c0, bmid + (size_t)c0 * H,
                                   Wmid + ((size_t)c0 * 129 + 128) * H, N, 0, 0, 1);
        gather_kernel<<<gw, TB>>>(1, N);                                  // g_h(+buf1) -> G
        gemm_kernel<<<gemmB, TB>>>(c1, bmid + (size_t)c1 * H,
                                   Wmid + ((size_t)c1 * 129 + 128) * H, N, 1, 1,
                                   (l < 2) ? 1 : 0);                      // conv5: no g_h
    }

    dot_kernel<<<gw, TB>>>(Wout, N);
    final_kernel<<<nB, TB>>>(x, Wout, bout, out, N);
}